// round 4
// baseline (speedup 1.0000x reference)
#include <cuda_runtime.h>
#include <cstdint>
#include <math.h>

#define TOKENS 2048
#define HIDDEN 2048
#define INTER  1408
#define NEXP   8
#define KT     32
#define LDA    36   // 32 + 4 pad (uint32): conflict-free frag loads

// ---------------- device scratch (no allocation) ----------------
__device__ int   g_counts[NEXP];
__device__ int   g_pairs[NEXP * TOKENS];               // encoded (t<<1)|slot
__device__ float g_wts[TOKENS * 2];                    // combine weight per (t,slot)
__device__ float g_hbuf[(size_t)TOKENS * 2 * INTER];   // gated intermediate
__device__ float g_ybuf[(size_t)TOKENS * 2 * HIDDEN];  // down-proj per (t,slot)

__device__ __forceinline__ uint32_t f2tf32(float f) {
    uint32_t u;
    asm("cvt.rna.tf32.f32 %0, %1;" : "=r"(u) : "f"(f));
    return u;
}

// m16n8k8 tf32 MMA (standard PTX, sm_80+)
__device__ __forceinline__ void mma_tf32(float* c, const uint32_t* a, const uint32_t* b) {
    asm volatile(
        "mma.sync.aligned.m16n8k8.row.col.f32.tf32.tf32.f32 "
        "{%0,%1,%2,%3}, {%4,%5,%6,%7}, {%8,%9}, {%0,%1,%2,%3};"
        : "+f"(c[0]), "+f"(c[1]), "+f"(c[2]), "+f"(c[3])
        : "r"(a[0]), "r"(a[1]), "r"(a[2]), "r"(a[3]), "r"(b[0]), "r"(b[1]));
}

// dynamic smem: rows[128] | A0 | B0 | A1 | B1  (each tile 128*LDA uint32)
#define TILE_U32 (128 * LDA)
#define SMEM_U32 (128 + 4 * TILE_U32)
#define SMEM_BYTES (SMEM_U32 * 4)

// ---------------- kernel 0: zero counters ----------------
__global__ void zero_counts_kernel() {
    if (threadIdx.x < NEXP) g_counts[threadIdx.x] = 0;
}

// ---------------- kernel 1: router ----------------
__global__ __launch_bounds__(256) void router_kernel(
    const float* __restrict__ x, const float* __restrict__ wr)
{
    int t = blockIdx.x;
    __shared__ float red[256][NEXP];
    float acc[NEXP];
#pragma unroll
    for (int e = 0; e < NEXP; e++) acc[e] = 0.f;
    const float* xr = x + (size_t)t * HIDDEN;
    for (int h = threadIdx.x; h < HIDDEN; h += 256) {
        float xv = xr[h];
        const float* w = wr + (size_t)h * NEXP;
#pragma unroll
        for (int e = 0; e < NEXP; e++) acc[e] += xv * w[e];
    }
#pragma unroll
    for (int e = 0; e < NEXP; e++) red[threadIdx.x][e] = acc[e];
    __syncthreads();
    for (int s = 128; s > 0; s >>= 1) {
        if (threadIdx.x < s) {
#pragma unroll
            for (int e = 0; e < NEXP; e++)
                red[threadIdx.x][e] += red[threadIdx.x + s][e];
        }
        __syncthreads();
    }
    if (threadIdx.x == 0) {
        float l[NEXP];
#pragma unroll
        for (int e = 0; e < NEXP; e++) l[e] = red[0][e];
        int i0 = 0;
#pragma unroll
        for (int e = 1; e < NEXP; e++) if (l[e] > l[i0]) i0 = e;
        int i1 = -1;
#pragma unroll
        for (int e = 0; e < NEXP; e++) {
            if (e == i0) continue;
            if (i1 < 0 || l[e] > l[i1]) i1 = e;
        }
        float w0 = 1.f / (1.f + __expf(l[i1] - l[i0]));
        float w1 = 1.f - w0;
        int p0 = atomicAdd(&g_counts[i0], 1);
        g_pairs[i0 * TOKENS + p0] = (t << 1);
        int p1 = atomicAdd(&g_counts[i1], 1);
        g_pairs[i1 * TOKENS + p1] = (t << 1) | 1;
        g_wts[(t << 1)]     = w0;
        g_wts[(t << 1) | 1] = w1;
    }
}

// ---------------- kernel 2: grouped gate+up GEMM, pipelined ----------------
__global__ __launch_bounds__(256, 1) void gateup_kernel(
    const float* __restrict__ x,
    const float* __restrict__ wg,
    const float* __restrict__ wu)
{
    const int e   = blockIdx.z;
    const int cnt = g_counts[e];
    const int m0  = blockIdx.y * 128;
    if (m0 >= cnt) return;
    const int n0  = blockIdx.x * 64;

    extern __shared__ __align__(16) uint32_t dsm[];
    int*      rows_sh = (int*)dsm;
    uint32_t* Abuf[2] = { dsm + 128,                dsm + 128 + 2 * TILE_U32 };
    uint32_t* Bbuf[2] = { dsm + 128 + TILE_U32,     dsm + 128 + 3 * TILE_U32 };

    const int tid  = threadIdx.x;
    const int wid  = tid >> 5;
    const int lane = tid & 31;
    const int gr   = lane >> 2;
    const int tg   = lane & 3;
    const int wm   = (wid & 1) * 64;
    const int wn   = (wid >> 1) * 32;

    if (tid < 128) {
        int m = m0 + tid;
        rows_sh[tid] = (m < cnt) ? g_pairs[e * TOKENS + m] : -1;
    }
    __syncthreads();

    const float* wge = wg + (size_t)e * HIDDEN * INTER;
    const float* wue = wu + (size_t)e * HIDDEN * INTER;

    // ---- fixed staging addresses (hoisted) ----
    const int ak4 = (tid & 7) * 4;           // A col within tile
    const float* aptr[4];
    int asto[4];
    bool aval[4];
#pragma unroll
    for (int i = 0; i < 4; i++) {
        int m  = (tid >> 3) + 32 * i;
        int pr = rows_sh[m];
        aval[i] = (pr >= 0);
        aptr[i] = aval[i] ? (x + (size_t)(pr >> 1) * HIDDEN + ak4) : x;
        asto[i] = m * LDA + ak4;
    }
    const int br0   = (tid & 31) * 4;        // B tile row (0..124)
    const int bhalf = (br0 >> 4) & 1;        // 0 gate / 1 up
    const int nn    = n0 + (br0 >> 5) * 16 + (br0 & 15);
    const float* bptr[4];
    int bk[4];
#pragma unroll
    for (int i = 0; i < 4; i++) {
        bk[i]   = (tid >> 5) + 8 * i;
        bptr[i] = (bhalf ? wue : wge) + (size_t)bk[i] * INTER + nn;
    }

    float acc[4][4][4];
#pragma unroll
    for (int i = 0; i < 4; i++)
#pragma unroll
        for (int j = 0; j < 4; j++)
#pragma unroll
            for (int c = 0; c < 4; c++) acc[i][j][c] = 0.f;

    // ---- prologue: load tile 0 into regs ----
    float4 pa[4], pb[4];
#pragma unroll
    for (int i = 0; i < 4; i++) {
        pa[i] = aval[i] ? *(const float4*)aptr[i] : make_float4(0.f, 0.f, 0.f, 0.f);
        pb[i] = *(const float4*)bptr[i];
    }

    const int NT = HIDDEN / KT;   // 64
    for (int kt = 0; kt < NT; kt++) {
        uint32_t* As = Abuf[kt & 1];
        uint32_t* Bs = Bbuf[kt & 1];

        // stage regs -> smem (converted)
#pragma unroll
        for (int i = 0; i < 4; i++) {
            uint4 o = make_uint4(f2tf32(pa[i].x), f2tf32(pa[i].y),
                                 f2tf32(pa[i].z), f2tf32(pa[i].w));
            *(uint4*)&As[asto[i]] = o;
        }
#pragma unroll
        for (int i = 0; i < 4; i++) {
            Bs[(br0 + 0) * LDA + bk[i]] = f2tf32(pb[i].x);
            Bs[(br0 + 1) * LDA + bk[i]] = f2tf32(pb[i].y);
            Bs[(br0 + 2) * LDA + bk[i]] = f2tf32(pb[i].z);
            Bs[(br0 + 3) * LDA + bk[i]] = f2tf32(pb[i].w);
        }
        __syncthreads();

        // prefetch next tile (LDGs in flight during MMA)
        if (kt + 1 < NT) {
#pragma unroll
            for (int i = 0; i < 4; i++) {
                aptr[i] += KT;
                bptr[i] += (size_t)KT * INTER;
                pa[i] = aval[i] ? *(const float4*)aptr[i] : make_float4(0.f, 0.f, 0.f, 0.f);
                pb[i] = *(const float4*)bptr[i];
            }
        }

        // MMA on current buffer
#pragma unroll
        for (int ks = 0; ks < 4; ks++) {
            const int k = ks * 8;
            uint32_t a[4][4];
#pragma unroll
            for (int mi = 0; mi < 4; mi++) {
                int r = wm + mi * 16 + gr;
                a[mi][0] = As[r * LDA + k + tg];
                a[mi][1] = As[(r + 8) * LDA + k + tg];
                a[mi][2] = As[r * LDA + k + tg + 4];
                a[mi][3] = As[(r + 8) * LDA + k + tg + 4];
            }
            uint32_t b[4][2];
#pragma unroll
            for (int nj = 0; nj < 4; nj++) {
                int r = wn + nj * 8 + gr;
                b[nj][0] = Bs[r * LDA + k + tg];
                b[nj][1] = Bs[r * LDA + k + tg + 4];
            }
#pragma unroll
            for (int mi = 0; mi < 4; mi++)
#pragma unroll
                for (int nj = 0; nj < 4; nj++)
                    mma_tf32(acc[mi][nj], a[mi], b[nj]);
        }
        __syncthreads();
    }

    // epilogue: silu(gate)*up*wt (nfrag 0,1 gate; 2,3 up at same cols)
    const int colbase = n0 + (wid >> 1) * 16 + 2 * tg;
#pragma unroll
    for (int mi = 0; mi < 4; mi++) {
#pragma unroll
        for (int half = 0; half < 2; half++) {
            int row = wm + mi * 16 + gr + half * 8;
            int pr  = rows_sh[row];
            if (pr < 0) continue;
            float wt = g_wts[pr];
            float* hrow = g_hbuf + (size_t)pr * INTER;
#pragma unroll
            for (int nj = 0; nj < 2; nj++) {
                float g0 = acc[mi][nj][half * 2 + 0];
                float g1 = acc[mi][nj][half * 2 + 1];
                float u0 = acc[mi][nj + 2][half * 2 + 0];
                float u1 = acc[mi][nj + 2][half * 2 + 1];
                float h0 = (g0 / (1.f + __expf(-g0))) * u0 * wt;
                float h1 = (g1 / (1.f + __expf(-g1))) * u1 * wt;
                *(float2*)&hrow[colbase + nj * 8] = make_float2(h0, h1);
            }
        }
    }
}

// ---------------- kernel 3: grouped down GEMM, pipelined ----------------
__global__ __launch_bounds__(256, 1) void down_kernel(const float* __restrict__ wd)
{
    const int e   = blockIdx.z;
    const int cnt = g_counts[e];
    const int m0  = blockIdx.y * 128;
    if (m0 >= cnt) return;
    const int n0  = blockIdx.x * 128;

    extern __shared__ __align__(16) uint32_t dsm[];
    int*      rows_sh = (int*)dsm;
    uint32_t* Abuf[2] = { dsm + 128,                dsm + 128 + 2 * TILE_U32 };
    uint32_t* Bbuf[2] = { dsm + 128 + TILE_U32,     dsm + 128 + 3 * TILE_U32 };

    const int tid  = threadIdx.x;
    const int wid  = tid >> 5;
    const int lane = tid & 31;
    const int gr   = lane >> 2;
    const int tg   = lane & 3;
    const int wm   = (wid & 1) * 64;
    const int wn   = (wid >> 1) * 32;

    if (tid < 128) {
        int m = m0 + tid;
        rows_sh[tid] = (m < cnt) ? g_pairs[e * TOKENS + m] : -1;
    }
    __syncthreads();

    const float* wde = wd + (size_t)e * INTER * HIDDEN;

    const int ak4 = (tid & 7) * 4;
    const float* aptr[4];
    int asto[4];
    bool aval[4];
#pragma unroll
    for (int i = 0; i < 4; i++) {
        int m  = (tid >> 3) + 32 * i;
        int pr = rows_sh[m];
        aval[i] = (pr >= 0);
        aptr[i] = aval[i] ? (g_hbuf + (size_t)pr * INTER + ak4) : g_hbuf;
        asto[i] = m * LDA + ak4;
    }
    const int br0 = (tid & 31) * 4;
    const int nn  = n0 + br0;
    const float* bptr[4];
    int bk[4];
#pragma unroll
    for (int i = 0; i < 4; i++) {
        bk[i]   = (tid >> 5) + 8 * i;
        bptr[i] = wde + (size_t)bk[i] * HIDDEN + nn;
    }

    float acc[4][4][4];
#pragma unroll
    for (int i = 0; i < 4; i++)
#pragma unroll
        for (int j = 0; j < 4; j++)
#pragma unroll
            for (int c = 0; c < 4; c++) acc[i][j][c] = 0.f;

    float4 pa[4], pb[4];
#pragma unroll
    for (int i = 0; i < 4; i++) {
        pa[i] = aval[i] ? *(const float4*)aptr[i] : make_float4(0.f, 0.f, 0.f, 0.f);
        pb[i] = *(const float4*)bptr[i];
    }

    const int NT = INTER / KT;   // 44
    for (int kt = 0; kt < NT; kt++) {
        uint32_t* As = Abuf[kt & 1];
        uint32_t* Bs = Bbuf[kt & 1];

#pragma unroll
        for (int i = 0; i < 4; i++) {
            uint4 o = make_uint4(f2tf32(pa[i].x), f2tf32(pa[i].y),
                                 f2tf32(pa[i].z), f2tf32(pa[i].w));
            *(uint4*)&As[asto[i]] = o;
        }
#pragma unroll
        for (int i = 0; i < 4; i++) {
            Bs[(br0 + 0) * LDA + bk[i]] = f2tf32(pb[i].x);
            Bs[(br0 + 1) * LDA + bk[i]] = f2tf32(pb[i].y);
            Bs[(br0 + 2) * LDA + bk[i]] = f2tf32(pb[i].z);
            Bs[(br0 + 3) * LDA + bk[i]] = f2tf32(pb[i].w);
        }
        __syncthreads();

        if (kt + 1 < NT) {
#pragma unroll
            for (int i = 0; i < 4; i++) {
                aptr[i] += KT;
                bptr[i] += (size_t)KT * HIDDEN;
                pa[i] = aval[i] ? *(const float4*)aptr[i] : make_float4(0.f, 0.f, 0.f, 0.f);
                pb[i] = *(const float4*)bptr[i];
            }
        }

#pragma unroll
        for (int ks = 0; ks < 4; ks++) {
            const int k = ks * 8;
            uint32_t a[4][4];
#pragma unroll
            for (int mi = 0; mi < 4; mi++) {
                int r = wm + mi * 16 + gr;
                a[mi][0] = As[r * LDA + k + tg];
                a[mi][1] = As[(r + 8) * LDA + k + tg];
                a[mi][2] = As[r * LDA + k + tg + 4];
                a[mi][3] = As[(r + 8) * LDA + k + tg + 4];
            }
            uint32_t b[4][2];
#pragma unroll
            for (int nj = 0; nj < 4; nj++) {
                int r = wn + nj * 8 + gr;
                b[nj][0] = Bs[r * LDA + k + tg];
                b[nj][1] = Bs[r * LDA + k + tg + 4];
            }
#pragma unroll
            for (int mi = 0; mi < 4; mi++)
#pragma unroll
                for (int nj = 0; nj < 4; nj++)
                    mma_tf32(acc[mi][nj], a[mi], b[nj]);
        }
        __syncthreads();
    }

    const int colbase = n0 + wn + 2 * tg;
#pragma unroll
    for (int mi = 0; mi < 4; mi++) {
#pragma unroll
        for (int half = 0; half < 2; half++) {
            int row = wm + mi * 16 + gr + half * 8;
            int pr  = rows_sh[row];
            if (pr < 0) continue;
            float* yrow = g_ybuf + (size_t)pr * HIDDEN;
#pragma unroll
            for (int nj = 0; nj < 4; nj++) {
                float v0 = acc[mi][nj][half * 2 + 0];
                float v1 = acc[mi][nj][half * 2 + 1];
                *(float2*)&yrow[colbase + nj * 8] = make_float2(v0, v1);
            }
        }
    }
}

// ---------------- kernel 4: combine slots ----------------
__global__ __launch_bounds__(256) void combine_kernel(float* __restrict__ out)
{
    size_t idx = (size_t)blockIdx.x * blockDim.x + threadIdx.x;
    size_t total = (size_t)TOKENS * HIDDEN / 4;
    if (idx >= total) return;
    size_t t = idx / (HIDDEN / 4);
    size_t c = idx % (HIDDEN / 4);
    const float4* y0 = (const float4*)(g_ybuf + (size_t)(t * 2)     * HIDDEN) + c;
    const float4* y1 = (const float4*)(g_ybuf + (size_t)(t * 2 + 1) * HIDDEN) + c;
    float4 a = *y0, b = *y1;
    ((float4*)out)[idx] = make_float4(a.x + b.x, a.y + b.y, a.z + b.z, a.w + b.w);
}

// ---------------- launch ----------------
extern "C" void kernel_launch(void* const* d_in, const int* in_sizes, int n_in,
                              void* d_out, int out_size)
{
    const float* x  = (const float*)d_in[0];
    const float* wr = (const float*)d_in[1];
    const float* wg = (const float*)d_in[2];
    const float* wu = (const float*)d_in[3];
    const float* wd = (const float*)d_in[4];
    float* out = (float*)d_out;

    cudaFuncSetAttribute(gateup_kernel, cudaFuncAttributeMaxDynamicSharedMemorySize, SMEM_BYTES);
    cudaFuncSetAttribute(down_kernel,  cudaFuncAttributeMaxDynamicSharedMemorySize, SMEM_BYTES);

    zero_counts_kernel<<<1, 32>>>();
    router_kernel<<<TOKENS, 256>>>(x, wr);

    dim3 g1(INTER / 64, TOKENS / 128, NEXP);    // 22 x 16 x 8
    gateup_kernel<<<g1, 256, SMEM_BYTES>>>(x, wg, wu);

    dim3 g2(HIDDEN / 128, TOKENS / 128, NEXP);  // 16 x 16 x 8
    down_kernel<<<g2, 256, SMEM_BYTES>>>(wd);

    size_t total4 = (size_t)TOKENS * HIDDEN / 4;
    combine_kernel<<<(unsigned)((total4 + 255) / 256), 256>>>(out);
}

// round 6
// speedup vs baseline: 2.2713x; 2.2713x over previous
#include <cuda_runtime.h>
#include <cstdint>
#include <math.h>

#define TOKENS 2048
#define HIDDEN 2048
#define INTER  1408
#define NEXP   8
#define KT     32
#define LDA    36   // 32 + 4 pad (uint32): conflict-free frag loads

// ---------------- device scratch (no allocation) ----------------
__device__ int      g_counts[NEXP];
__device__ int      g_pairs[NEXP * TOKENS];               // encoded (t<<1)|slot
__device__ float    g_wts[TOKENS * 2];                    // combine weight per (t,slot)
__device__ uint32_t g_x_tf[(size_t)TOKENS * HIDDEN];      // x converted to tf32
__device__ uint32_t g_wg_t[(size_t)NEXP * HIDDEN * INTER]; // w_gate tf32, [e][n][k]
__device__ uint32_t g_wu_t[(size_t)NEXP * HIDDEN * INTER]; // w_up   tf32, [e][n][k]
__device__ uint32_t g_wd_t[(size_t)NEXP * INTER * HIDDEN]; // w_down tf32, [e][n][k]
__device__ uint32_t g_hbuf[(size_t)TOKENS * 2 * INTER];   // gated intermediate (tf32)
__device__ float    g_ybuf[(size_t)TOKENS * 2 * HIDDEN];  // down-proj per (t,slot)

__device__ __forceinline__ uint32_t f2tf32(float f) {
    uint32_t u;
    asm("cvt.rna.tf32.f32 %0, %1;" : "=r"(u) : "f"(f));
    return u;
}

// m16n8k8 tf32 MMA (standard PTX, sm_80+)
__device__ __forceinline__ void mma_tf32(float* c, const uint32_t* a, const uint32_t* b) {
    asm volatile(
        "mma.sync.aligned.m16n8k8.row.col.f32.tf32.tf32.f32 "
        "{%0,%1,%2,%3}, {%4,%5,%6,%7}, {%8,%9}, {%0,%1,%2,%3};"
        : "+f"(c[0]), "+f"(c[1]), "+f"(c[2]), "+f"(c[3])
        : "r"(a[0]), "r"(a[1]), "r"(a[2]), "r"(a[3]), "r"(b[0]), "r"(b[1]));
}

__device__ __forceinline__ void cp16(uint32_t dst, const void* src, int sz) {
    asm volatile("cp.async.cg.shared.global [%0], [%1], 16, %2;"
                 :: "r"(dst), "l"(src), "r"(sz) : "memory");
}
#define CP_COMMIT() asm volatile("cp.async.commit_group;" ::: "memory")
#define CP_WAIT0()  asm volatile("cp.async.wait_group 0;" ::: "memory")

// dynamic smem: rows[128] | A0 | B0 | A1 | B1  (each tile 128*LDA uint32)
#define TILE_U32 (128 * LDA)
#define SMEM_U32 (128 + 4 * TILE_U32)
#define SMEM_BYTES (SMEM_U32 * 4)

// ---------------- kernel 0: zero counters ----------------
__global__ void zero_counts_kernel() {
    if (threadIdx.x < NEXP) g_counts[threadIdx.x] = 0;
}

// ---------------- preprocessing: transpose+convert weights ----------------
// src [e][K][N] (n contiguous) -> dst [e][N][K] (k contiguous), tf32 bits.
// dst selected DEVICE-SIDE (device-global symbols must not be passed from host).
__global__ __launch_bounds__(256) void transpose_cvt_kernel(
    const float* __restrict__ src, int which, int K, int N)
{
    uint32_t* dst = (which == 0) ? g_wg_t : (which == 1) ? g_wu_t : g_wd_t;
    __shared__ uint32_t tile[32][33];
    const size_t eoff = (size_t)blockIdx.z * K * N;
    const int n0 = blockIdx.x * 32;
    const int k0 = blockIdx.y * 32;
    const int tx = threadIdx.x & 31;
    const int ty = threadIdx.x >> 5;  // 0..7
#pragma unroll
    for (int j = 0; j < 32; j += 8)
        tile[ty + j][tx] = f2tf32(src[eoff + (size_t)(k0 + ty + j) * N + n0 + tx]);
    __syncthreads();
#pragma unroll
    for (int j = 0; j < 32; j += 8)
        dst[eoff + (size_t)(n0 + ty + j) * K + k0 + tx] = tile[tx][ty + j];
}

// x -> tf32 (layout unchanged)
__global__ __launch_bounds__(256) void cvt_x_kernel(const float* __restrict__ src)
{
    size_t i = ((size_t)blockIdx.x * blockDim.x + threadIdx.x) * 4;
    float4 v = *(const float4*)(src + i);
    uint4 o = make_uint4(f2tf32(v.x), f2tf32(v.y), f2tf32(v.z), f2tf32(v.w));
    *(uint4*)(g_x_tf + i) = o;
}

// ---------------- kernel 1: router ----------------
__global__ __launch_bounds__(256) void router_kernel(
    const float* __restrict__ x, const float* __restrict__ wr)
{
    int t = blockIdx.x;
    __shared__ float red[256][NEXP];
    float acc[NEXP];
#pragma unroll
    for (int e = 0; e < NEXP; e++) acc[e] = 0.f;
    const float* xr = x + (size_t)t * HIDDEN;
    for (int h = threadIdx.x; h < HIDDEN; h += 256) {
        float xv = xr[h];
        const float* w = wr + (size_t)h * NEXP;
#pragma unroll
        for (int e = 0; e < NEXP; e++) acc[e] += xv * w[e];
    }
#pragma unroll
    for (int e = 0; e < NEXP; e++) red[threadIdx.x][e] = acc[e];
    __syncthreads();
    for (int s = 128; s > 0; s >>= 1) {
        if (threadIdx.x < s) {
#pragma unroll
            for (int e = 0; e < NEXP; e++)
                red[threadIdx.x][e] += red[threadIdx.x + s][e];
        }
        __syncthreads();
    }
    if (threadIdx.x == 0) {
        float l[NEXP];
#pragma unroll
        for (int e = 0; e < NEXP; e++) l[e] = red[0][e];
        int i0 = 0;
#pragma unroll
        for (int e = 1; e < NEXP; e++) if (l[e] > l[i0]) i0 = e;
        int i1 = -1;
#pragma unroll
        for (int e = 0; e < NEXP; e++) {
            if (e == i0) continue;
            if (i1 < 0 || l[e] > l[i1]) i1 = e;
        }
        float w0 = 1.f / (1.f + __expf(l[i1] - l[i0]));
        float w1 = 1.f - w0;
        int p0 = atomicAdd(&g_counts[i0], 1);
        g_pairs[i0 * TOKENS + p0] = (t << 1);
        int p1 = atomicAdd(&g_counts[i1], 1);
        g_pairs[i1 * TOKENS + p1] = (t << 1) | 1;
        g_wts[(t << 1)]     = w0;
        g_wts[(t << 1) | 1] = w1;
    }
}

// ---------------- kernel 2: grouped gate+up GEMM, cp.async pipelined ----------------
__global__ __launch_bounds__(256, 2) void gateup_kernel()
{
    const int e   = blockIdx.z;
    const int cnt = g_counts[e];
    const int m0  = blockIdx.y * 128;
    if (m0 >= cnt) return;
    const int n0  = blockIdx.x * 64;

    extern __shared__ __align__(16) uint32_t dsm[];
    int* rows_sh = (int*)dsm;
    const uint32_t sb = (uint32_t)__cvta_generic_to_shared(dsm);

    const int tid  = threadIdx.x;
    const int wid  = tid >> 5;
    const int lane = tid & 31;
    const int gr   = lane >> 2;
    const int tg   = lane & 3;
    const int wm   = (wid & 1) * 64;
    const int wn   = (wid >> 1) * 32;

    if (tid < 128) {
        int m = m0 + tid;
        rows_sh[tid] = (m < cnt) ? g_pairs[e * TOKENS + m] : -1;
    }
    __syncthreads();

    const size_t eoff = (size_t)e * HIDDEN * INTER;
    const int kc = (tid & 7) * 4;   // common k-offset for all 4 chunks

    // staging sources/dests (fixed per thread)
    const uint32_t* asrc[4];
    int  asz[4];
    uint32_t adst[4];               // byte offset within A tile
#pragma unroll
    for (int i = 0; i < 4; i++) {
        int m  = (tid >> 3) + 32 * i;
        int pr = rows_sh[m];
        asz[i]  = (pr >= 0) ? 16 : 0;
        asrc[i] = g_x_tf + (size_t)((pr >= 0) ? (pr >> 1) : 0) * HIDDEN + kc;
        adst[i] = (uint32_t)(m * LDA + kc) * 4;
    }
    const uint32_t* bsrc[4];
    uint32_t bdst[4];
#pragma unroll
    for (int i = 0; i < 4; i++) {
        int r    = (tid >> 3) + 32 * i;      // B tile row 0..127
        int half = (r >> 4) & 1;             // 0 gate / 1 up
        int nn   = n0 + (r >> 5) * 16 + (r & 15);
        bsrc[i]  = (half ? g_wu_t : g_wg_t) + eoff + (size_t)nn * HIDDEN + kc;
        bdst[i]  = (uint32_t)(r * LDA + kc) * 4;
    }

    float acc[4][4][4];
#pragma unroll
    for (int i = 0; i < 4; i++)
#pragma unroll
        for (int j = 0; j < 4; j++)
#pragma unroll
            for (int c = 0; c < 4; c++) acc[i][j][c] = 0.f;

    // prologue: stage 0
    {
        uint32_t ab = sb + 128 * 4;
        uint32_t bb = ab + TILE_U32 * 4;
#pragma unroll
        for (int i = 0; i < 4; i++) cp16(ab + adst[i], asrc[i], asz[i]);
#pragma unroll
        for (int i = 0; i < 4; i++) cp16(bb + bdst[i], bsrc[i], 16);
        CP_COMMIT();
    }

    const int NT = HIDDEN / KT;   // 64
    for (int kt = 0; kt < NT; kt++) {
        CP_WAIT0();
        __syncthreads();

        if (kt + 1 < NT) {
            int buf = (kt + 1) & 1;
            uint32_t ab = sb + (128 + buf * 2 * TILE_U32) * 4;
            uint32_t bb = ab + TILE_U32 * 4;
            size_t ko = (size_t)(kt + 1) * KT;
#pragma unroll
            for (int i = 0; i < 4; i++) cp16(ab + adst[i], asrc[i] + ko, asz[i]);
#pragma unroll
            for (int i = 0; i < 4; i++) cp16(bb + bdst[i], bsrc[i] + ko, 16);
            CP_COMMIT();
        }

        const uint32_t* As = dsm + 128 + (kt & 1) * 2 * TILE_U32;
        const uint32_t* Bs = As + TILE_U32;
#pragma unroll
        for (int ks = 0; ks < 4; ks++) {
            const int k = ks * 8;
            uint32_t a[4][4];
#pragma unroll
            for (int mi = 0; mi < 4; mi++) {
                int r = wm + mi * 16 + gr;
                a[mi][0] = As[r * LDA + k + tg];
                a[mi][1] = As[(r + 8) * LDA + k + tg];
                a[mi][2] = As[r * LDA + k + tg + 4];
                a[mi][3] = As[(r + 8) * LDA + k + tg + 4];
            }
            uint32_t b[4][2];
#pragma unroll
            for (int nj = 0; nj < 4; nj++) {
                int r = wn + nj * 8 + gr;
                b[nj][0] = Bs[r * LDA + k + tg];
                b[nj][1] = Bs[r * LDA + k + tg + 4];
            }
#pragma unroll
            for (int mi = 0; mi < 4; mi++)
#pragma unroll
                for (int nj = 0; nj < 4; nj++)
                    mma_tf32(acc[mi][nj], a[mi], b[nj]);
        }
        __syncthreads();
    }

    // epilogue: silu(gate)*up*wt -> hbuf (tf32 bits)
    const int colbase = n0 + (wid >> 1) * 16 + 2 * tg;
#pragma unroll
    for (int mi = 0; mi < 4; mi++) {
#pragma unroll
        for (int half = 0; half < 2; half++) {
            int row = wm + mi * 16 + gr + half * 8;
            int pr  = rows_sh[row];
            if (pr < 0) continue;
            float wt = g_wts[pr];
            uint32_t* hrow = g_hbuf + (size_t)pr * INTER;
#pragma unroll
            for (int nj = 0; nj < 2; nj++) {
                float g0 = acc[mi][nj][half * 2 + 0];
                float g1 = acc[mi][nj][half * 2 + 1];
                float u0 = acc[mi][nj + 2][half * 2 + 0];
                float u1 = acc[mi][nj + 2][half * 2 + 1];
                float h0 = (g0 / (1.f + __expf(-g0))) * u0 * wt;
                float h1 = (g1 / (1.f + __expf(-g1))) * u1 * wt;
                uint2 o = make_uint2(f2tf32(h0), f2tf32(h1));
                *(uint2*)&hrow[colbase + nj * 8] = o;
            }
        }
    }
}

// ---------------- kernel 3: grouped down GEMM, cp.async pipelined ----------------
__global__ __launch_bounds__(256, 2) void down_kernel()
{
    const int e   = blockIdx.z;
    const int cnt = g_counts[e];
    const int m0  = blockIdx.y * 128;
    if (m0 >= cnt) return;
    const int n0  = blockIdx.x * 128;

    extern __shared__ __align__(16) uint32_t dsm[];
    int* rows_sh = (int*)dsm;
    const uint32_t sb = (uint32_t)__cvta_generic_to_shared(dsm);

    const int tid  = threadIdx.x;
    const int wid  = tid >> 5;
    const int lane = tid & 31;
    const int gr   = lane >> 2;
    const int tg   = lane & 3;
    const int wm   = (wid & 1) * 64;
    const int wn   = (wid >> 1) * 32;

    if (tid < 128) {
        int m = m0 + tid;
        rows_sh[tid] = (m < cnt) ? g_pairs[e * TOKENS + m] : -1;
    }
    __syncthreads();

    const size_t eoff = (size_t)e * INTER * HIDDEN;
    const int kc = (tid & 7) * 4;

    const uint32_t* asrc[4];
    int  asz[4];
    uint32_t adst[4];
#pragma unroll
    for (int i = 0; i < 4; i++) {
        int m  = (tid >> 3) + 32 * i;
        int pr = rows_sh[m];
        asz[i]  = (pr >= 0) ? 16 : 0;
        asrc[i] = g_hbuf + (size_t)((pr >= 0) ? pr : 0) * INTER + kc;
        adst[i] = (uint32_t)(m * LDA + kc) * 4;
    }
    const uint32_t* bsrc[4];
    uint32_t bdst[4];
#pragma unroll
    for (int i = 0; i < 4; i++) {
        int r   = (tid >> 3) + 32 * i;
        int nn  = n0 + r;
        bsrc[i] = g_wd_t + eoff + (size_t)nn * INTER + kc;
        bdst[i] = (uint32_t)(r * LDA + kc) * 4;
    }

    float acc[4][4][4];
#pragma unroll
    for (int i = 0; i < 4; i++)
#pragma unroll
        for (int j = 0; j < 4; j++)
#pragma unroll
            for (int c = 0; c < 4; c++) acc[i][j][c] = 0.f;

    {
        uint32_t ab = sb + 128 * 4;
        uint32_t bb = ab + TILE_U32 * 4;
#pragma unroll
        for (int i = 0; i < 4; i++) cp16(ab + adst[i], asrc[i], asz[i]);
#pragma unroll
        for (int i = 0; i < 4; i++) cp16(bb + bdst[i], bsrc[i], 16);
        CP_COMMIT();
    }

    const int NT = INTER / KT;   // 44
    for (int kt = 0; kt < NT; kt++) {
        CP_WAIT0();
        __syncthreads();

        if (kt + 1 < NT) {
            int buf = (kt + 1) & 1;
            uint32_t ab = sb + (128 + buf * 2 * TILE_U32) * 4;
            uint32_t bb = ab + TILE_U32 * 4;
            size_t ko = (size_t)(kt + 1) * KT;
#pragma unroll
            for (int i = 0; i < 4; i++) cp16(ab + adst[i], asrc[i] + ko, asz[i]);
#pragma unroll
            for (int i = 0; i < 4; i++) cp16(bb + bdst[i], bsrc[i] + ko, 16);
            CP_COMMIT();
        }

        const uint32_t* As = dsm + 128 + (kt & 1) * 2 * TILE_U32;
        const uint32_t* Bs = As + TILE_U32;
#pragma unroll
        for (int ks = 0; ks < 4; ks++) {
            const int k = ks * 8;
            uint32_t a[4][4];
#pragma unroll
            for (int mi = 0; mi < 4; mi++) {
                int r = wm + mi * 16 + gr;
                a[mi][0] = As[r * LDA + k + tg];
                a[mi][1] = As[(r + 8) * LDA + k + tg];
                a[mi][2] = As[r * LDA + k + tg + 4];
                a[mi][3] = As[(r + 8) * LDA + k + tg + 4];
            }
            uint32_t b[4][2];
#pragma unroll
            for (int nj = 0; nj < 4; nj++) {
                int r = wn + nj * 8 + gr;
                b[nj][0] = Bs[r * LDA + k + tg];
                b[nj][1] = Bs[r * LDA + k + tg + 4];
            }
#pragma unroll
            for (int mi = 0; mi < 4; mi++)
#pragma unroll
                for (int nj = 0; nj < 4; nj++)
                    mma_tf32(acc[mi][nj], a[mi], b[nj]);
        }
        __syncthreads();
    }

    const int colbase = n0 + wn + 2 * tg;
#pragma unroll
    for (int mi = 0; mi < 4; mi++) {
#pragma unroll
        for (int half = 0; half < 2; half++) {
            int row = wm + mi * 16 + gr + half * 8;
            int pr  = rows_sh[row];
            if (pr < 0) continue;
            float* yrow = g_ybuf + (size_t)pr * HIDDEN;
#pragma unroll
            for (int nj = 0; nj < 4; nj++) {
                float v0 = acc[mi][nj][half * 2 + 0];
                float v1 = acc[mi][nj][half * 2 + 1];
                *(float2*)&yrow[colbase + nj * 8] = make_float2(v0, v1);
            }
        }
    }
}

// ---------------- kernel 4: combine slots ----------------
__global__ __launch_bounds__(256) void combine_kernel(float* __restrict__ out)
{
    size_t idx = (size_t)blockIdx.x * blockDim.x + threadIdx.x;
    size_t total = (size_t)TOKENS * HIDDEN / 4;
    if (idx >= total) return;
    size_t t = idx / (HIDDEN / 4);
    size_t c = idx % (HIDDEN / 4);
    const float4* y0 = (const float4*)(g_ybuf + (size_t)(t * 2)     * HIDDEN) + c;
    const float4* y1 = (const float4*)(g_ybuf + (size_t)(t * 2 + 1) * HIDDEN) + c;
    float4 a = *y0, b = *y1;
    ((float4*)out)[idx] = make_float4(a.x + b.x, a.y + b.y, a.z + b.z, a.w + b.w);
}

// ---------------- launch ----------------
extern "C" void kernel_launch(void* const* d_in, const int* in_sizes, int n_in,
                              void* d_out, int out_size)
{
    const float* x  = (const float*)d_in[0];
    const float* wr = (const float*)d_in[1];
    const float* wg = (const float*)d_in[2];
    const float* wu = (const float*)d_in[3];
    const float* wd = (const float*)d_in[4];
    float* out = (float*)d_out;

    cudaFuncSetAttribute(gateup_kernel, cudaFuncAttributeMaxDynamicSharedMemorySize, SMEM_BYTES);
    cudaFuncSetAttribute(down_kernel,  cudaFuncAttributeMaxDynamicSharedMemorySize, SMEM_BYTES);

    zero_counts_kernel<<<1, 32>>>();
    router_kernel<<<TOKENS, 256>>>(x, wr);

    // preprocessing: tf32 conversion + weight transpose to [e][n][k]
    // (dst resolved device-side; device-global symbols must not be passed from host)
    cvt_x_kernel<<<(TOKENS * HIDDEN) / (256 * 4), 256>>>(x);
    transpose_cvt_kernel<<<dim3(INTER / 32, HIDDEN / 32, NEXP), 256>>>(wg, 0, HIDDEN, INTER);
    transpose_cvt_kernel<<<dim3(INTER / 32, HIDDEN / 32, NEXP), 256>>>(wu, 1, HIDDEN, INTER);
    transpose_cvt_kernel<<<dim3(HIDDEN / 32, INTER / 32, NEXP), 256>>>(wd, 2, INTER, HIDDEN);

    dim3 g1(INTER / 64, TOKENS / 128, NEXP);    // 22 x 16 x 8
    gateup_kernel<<<g1, 256, SMEM_BYTES>>>();

    dim3 g2(HIDDEN / 128, TOKENS / 128, NEXP);  // 16 x 16 x 8
    down_kernel<<<g2, 256, SMEM_BYTES>>>();

    size_t total4 = (size_t)TOKENS * HIDDEN / 4;
    combine_kernel<<<(unsigned)((total4 + 255) / 256), 256>>>(out);
}

// round 7
// speedup vs baseline: 2.2714x; 1.0000x over previous
#include <cuda_runtime.h>
#include <cstdint>
#include <math.h>

#define TOKENS 2048
#define HIDDEN 2048
#define INTER  1408
#define NEXP   8
#define KT     32
#define LDA    36   // 32 + 4 pad (uint32): conflict-free frag loads
#define STAGES 3

// ---------------- device scratch (no allocation) ----------------
__device__ int      g_counts[NEXP];
__device__ int      g_pairs[NEXP * TOKENS];               // encoded (t<<1)|slot
__device__ float    g_wts[TOKENS * 2];                    // combine weight per (t,slot)
__device__ uint32_t g_x_tf[(size_t)TOKENS * HIDDEN];      // x converted to tf32
__device__ uint32_t g_wg_t[(size_t)NEXP * HIDDEN * INTER]; // w_gate tf32, [e][n][k]
__device__ uint32_t g_wu_t[(size_t)NEXP * HIDDEN * INTER]; // w_up   tf32, [e][n][k]
__device__ uint32_t g_wd_t[(size_t)NEXP * INTER * HIDDEN]; // w_down tf32, [e][n][k]
__device__ uint32_t g_hbuf[(size_t)TOKENS * 2 * INTER];   // gated intermediate (tf32)
__device__ float    g_ybuf[(size_t)TOKENS * 2 * HIDDEN];  // down-proj per (t,slot)

__device__ __forceinline__ uint32_t f2tf32(float f) {
    uint32_t u;
    asm("cvt.rna.tf32.f32 %0, %1;" : "=r"(u) : "f"(f));
    return u;
}

// m16n8k8 tf32 MMA (standard PTX, sm_80+)
__device__ __forceinline__ void mma_tf32(float* c, const uint32_t* a, const uint32_t* b) {
    asm volatile(
        "mma.sync.aligned.m16n8k8.row.col.f32.tf32.tf32.f32 "
        "{%0,%1,%2,%3}, {%4,%5,%6,%7}, {%8,%9}, {%0,%1,%2,%3};"
        : "+f"(c[0]), "+f"(c[1]), "+f"(c[2]), "+f"(c[3])
        : "r"(a[0]), "r"(a[1]), "r"(a[2]), "r"(a[3]), "r"(b[0]), "r"(b[1]));
}

__device__ __forceinline__ void cp16(uint32_t dst, const void* src, int sz) {
    asm volatile("cp.async.cg.shared.global [%0], [%1], 16, %2;"
                 :: "r"(dst), "l"(src), "r"(sz) : "memory");
}
#define CP_COMMIT() asm volatile("cp.async.commit_group;" ::: "memory")
#define CP_WAIT1()  asm volatile("cp.async.wait_group 1;" ::: "memory")

// dynamic smem: rows[128] | {A,B} x STAGES  (each tile 128*LDA uint32)
#define TILE_U32 (128 * LDA)
#define SMEM_U32 (128 + 2 * STAGES * TILE_U32)
#define SMEM_BYTES (SMEM_U32 * 4)

// ---------------- kernel 0: zero counters ----------------
__global__ void zero_counts_kernel() {
    if (threadIdx.x < NEXP) g_counts[threadIdx.x] = 0;
}

// ---------------- preprocessing: transpose+convert weights ----------------
// src [e][K][N] (n contiguous) -> dst [e][N][K] (k contiguous), tf32 bits.
// dst selected DEVICE-SIDE (device-global symbols must not be passed from host).
__global__ __launch_bounds__(256) void transpose_cvt_kernel(
    const float* __restrict__ src, int which, int K, int N)
{
    uint32_t* dst = (which == 0) ? g_wg_t : (which == 1) ? g_wu_t : g_wd_t;
    __shared__ uint32_t tile[32][33];
    const size_t eoff = (size_t)blockIdx.z * K * N;
    const int n0 = blockIdx.x * 32;
    const int k0 = blockIdx.y * 32;
    const int tx = threadIdx.x & 31;
    const int ty = threadIdx.x >> 5;  // 0..7
#pragma unroll
    for (int j = 0; j < 32; j += 8)
        tile[ty + j][tx] = f2tf32(src[eoff + (size_t)(k0 + ty + j) * N + n0 + tx]);
    __syncthreads();
#pragma unroll
    for (int j = 0; j < 32; j += 8)
        dst[eoff + (size_t)(n0 + ty + j) * K + k0 + tx] = tile[tx][ty + j];
}

// x -> tf32 (layout unchanged)
__global__ __launch_bounds__(256) void cvt_x_kernel(const float* __restrict__ src)
{
    size_t i = ((size_t)blockIdx.x * blockDim.x + threadIdx.x) * 4;
    float4 v = *(const float4*)(src + i);
    uint4 o = make_uint4(f2tf32(v.x), f2tf32(v.y), f2tf32(v.z), f2tf32(v.w));
    *(uint4*)(g_x_tf + i) = o;
}

// ---------------- kernel 1: router ----------------
__global__ __launch_bounds__(256) void router_kernel(
    const float* __restrict__ x, const float* __restrict__ wr)
{
    int t = blockIdx.x;
    __shared__ float red[256][NEXP];
    float acc[NEXP];
#pragma unroll
    for (int e = 0; e < NEXP; e++) acc[e] = 0.f;
    const float* xr = x + (size_t)t * HIDDEN;
    for (int h = threadIdx.x; h < HIDDEN; h += 256) {
        float xv = xr[h];
        const float* w = wr + (size_t)h * NEXP;
#pragma unroll
        for (int e = 0; e < NEXP; e++) acc[e] += xv * w[e];
    }
#pragma unroll
    for (int e = 0; e < NEXP; e++) red[threadIdx.x][e] = acc[e];
    __syncthreads();
    for (int s = 128; s > 0; s >>= 1) {
        if (threadIdx.x < s) {
#pragma unroll
            for (int e = 0; e < NEXP; e++)
                red[threadIdx.x][e] += red[threadIdx.x + s][e];
        }
        __syncthreads();
    }
    if (threadIdx.x == 0) {
        float l[NEXP];
#pragma unroll
        for (int e = 0; e < NEXP; e++) l[e] = red[0][e];
        int i0 = 0;
#pragma unroll
        for (int e = 1; e < NEXP; e++) if (l[e] > l[i0]) i0 = e;
        int i1 = -1;
#pragma unroll
        for (int e = 0; e < NEXP; e++) {
            if (e == i0) continue;
            if (i1 < 0 || l[e] > l[i1]) i1 = e;
        }
        float w0 = 1.f / (1.f + __expf(l[i1] - l[i0]));
        float w1 = 1.f - w0;
        int p0 = atomicAdd(&g_counts[i0], 1);
        g_pairs[i0 * TOKENS + p0] = (t << 1);
        int p1 = atomicAdd(&g_counts[i1], 1);
        g_pairs[i1 * TOKENS + p1] = (t << 1) | 1;
        g_wts[(t << 1)]     = w0;
        g_wts[(t << 1) | 1] = w1;
    }
}

// ---------------- kernel 2: grouped gate+up GEMM, 3-stage cp.async ----------------
__global__ __launch_bounds__(256, 2) void gateup_kernel()
{
    const int e   = blockIdx.z;
    const int cnt = g_counts[e];
    const int m0  = blockIdx.y * 128;
    if (m0 >= cnt) return;
    const int n0  = blockIdx.x * 64;

    extern __shared__ __align__(16) uint32_t dsm[];
    int* rows_sh = (int*)dsm;
    const uint32_t sb = (uint32_t)__cvta_generic_to_shared(dsm);

    const int tid  = threadIdx.x;
    const int wid  = tid >> 5;
    const int lane = tid & 31;
    const int gr   = lane >> 2;
    const int tg   = lane & 3;
    const int wm   = (wid & 1) * 64;
    const int wn   = (wid >> 1) * 32;

    if (tid < 128) {
        int m = m0 + tid;
        rows_sh[tid] = (m < cnt) ? g_pairs[e * TOKENS + m] : -1;
    }
    __syncthreads();

    const size_t eoff = (size_t)e * HIDDEN * INTER;
    const int kc = (tid & 7) * 4;   // common k-offset for all 4 chunks

    // staging sources/dests (fixed per thread)
    const uint32_t* asrc[4];
    int  asz[4];
    uint32_t adst[4];               // byte offset within A tile
#pragma unroll
    for (int i = 0; i < 4; i++) {
        int m  = (tid >> 3) + 32 * i;
        int pr = rows_sh[m];
        asz[i]  = (pr >= 0) ? 16 : 0;
        asrc[i] = g_x_tf + (size_t)((pr >= 0) ? (pr >> 1) : 0) * HIDDEN + kc;
        adst[i] = (uint32_t)(m * LDA + kc) * 4;
    }
    const uint32_t* bsrc[4];
    uint32_t bdst[4];
#pragma unroll
    for (int i = 0; i < 4; i++) {
        int r    = (tid >> 3) + 32 * i;      // B tile row 0..127
        int half = (r >> 4) & 1;             // 0 gate / 1 up
        int nn   = n0 + (r >> 5) * 16 + (r & 15);
        bsrc[i]  = (half ? g_wu_t : g_wg_t) + eoff + (size_t)nn * HIDDEN + kc;
        bdst[i]  = (uint32_t)(r * LDA + kc) * 4;
    }

    float acc[4][4][4];
#pragma unroll
    for (int i = 0; i < 4; i++)
#pragma unroll
        for (int j = 0; j < 4; j++)
#pragma unroll
            for (int c = 0; c < 4; c++) acc[i][j][c] = 0.f;

    // prologue: stage tiles 0..STAGES-2
#pragma unroll
    for (int s = 0; s < STAGES - 1; s++) {
        uint32_t ab = sb + (128 + s * 2 * TILE_U32) * 4;
        uint32_t bb = ab + TILE_U32 * 4;
        size_t ko = (size_t)s * KT;
#pragma unroll
        for (int i = 0; i < 4; i++) cp16(ab + adst[i], asrc[i] + ko, asz[i]);
#pragma unroll
        for (int i = 0; i < 4; i++) cp16(bb + bdst[i], bsrc[i] + ko, 16);
        CP_COMMIT();
    }

    const int NT = HIDDEN / KT;   // 64
    int rd = 0;                    // read buffer for tile kt
    int wr = STAGES - 1;           // write buffer for tile kt+STAGES-1
    for (int kt = 0; kt < NT; kt++) {
        CP_WAIT1();                // oldest pending group (tile kt) done
        __syncthreads();           // all copies visible + prior MMA reads done

        if (kt + STAGES - 1 < NT) {
            uint32_t ab = sb + (128 + wr * 2 * TILE_U32) * 4;
            uint32_t bb = ab + TILE_U32 * 4;
            size_t ko = (size_t)(kt + STAGES - 1) * KT;
#pragma unroll
            for (int i = 0; i < 4; i++) cp16(ab + adst[i], asrc[i] + ko, asz[i]);
#pragma unroll
            for (int i = 0; i < 4; i++) cp16(bb + bdst[i], bsrc[i] + ko, 16);
        }
        CP_COMMIT();               // commit every iter (empty ok) for group counting

        const uint32_t* As = dsm + 128 + rd * 2 * TILE_U32;
        const uint32_t* Bs = As + TILE_U32;
#pragma unroll
        for (int ks = 0; ks < 4; ks++) {
            const int k = ks * 8;
            uint32_t a[4][4];
#pragma unroll
            for (int mi = 0; mi < 4; mi++) {
                int r = wm + mi * 16 + gr;
                a[mi][0] = As[r * LDA + k + tg];
                a[mi][1] = As[(r + 8) * LDA + k + tg];
                a[mi][2] = As[r * LDA + k + tg + 4];
                a[mi][3] = As[(r + 8) * LDA + k + tg + 4];
            }
            uint32_t b[4][2];
#pragma unroll
            for (int nj = 0; nj < 4; nj++) {
                int r = wn + nj * 8 + gr;
                b[nj][0] = Bs[r * LDA + k + tg];
                b[nj][1] = Bs[r * LDA + k + tg + 4];
            }
#pragma unroll
            for (int mi = 0; mi < 4; mi++)
#pragma unroll
                for (int nj = 0; nj < 4; nj++)
                    mma_tf32(acc[mi][nj], a[mi], b[nj]);
        }
        rd = (rd == STAGES - 1) ? 0 : rd + 1;
        wr = (wr == STAGES - 1) ? 0 : wr + 1;
    }

    // epilogue: silu(gate)*up*wt -> hbuf (tf32 bits)
    const int colbase = n0 + (wid >> 1) * 16 + 2 * tg;
#pragma unroll
    for (int mi = 0; mi < 4; mi++) {
#pragma unroll
        for (int half = 0; half < 2; half++) {
            int row = wm + mi * 16 + gr + half * 8;
            int pr  = rows_sh[row];
            if (pr < 0) continue;
            float wt = g_wts[pr];
            uint32_t* hrow = g_hbuf + (size_t)pr * INTER;
#pragma unroll
            for (int nj = 0; nj < 2; nj++) {
                float g0 = acc[mi][nj][half * 2 + 0];
                float g1 = acc[mi][nj][half * 2 + 1];
                float u0 = acc[mi][nj + 2][half * 2 + 0];
                float u1 = acc[mi][nj + 2][half * 2 + 1];
                float h0 = (g0 / (1.f + __expf(-g0))) * u0 * wt;
                float h1 = (g1 / (1.f + __expf(-g1))) * u1 * wt;
                uint2 o = make_uint2(f2tf32(h0), f2tf32(h1));
                *(uint2*)&hrow[colbase + nj * 8] = o;
            }
        }
    }
}

// ---------------- kernel 3: grouped down GEMM, 3-stage cp.async ----------------
__global__ __launch_bounds__(256, 2) void down_kernel()
{
    const int e   = blockIdx.z;
    const int cnt = g_counts[e];
    const int m0  = blockIdx.y * 128;
    if (m0 >= cnt) return;
    const int n0  = blockIdx.x * 128;

    extern __shared__ __align__(16) uint32_t dsm[];
    int* rows_sh = (int*)dsm;
    const uint32_t sb = (uint32_t)__cvta_generic_to_shared(dsm);

    const int tid  = threadIdx.x;
    const int wid  = tid >> 5;
    const int lane = tid & 31;
    const int gr   = lane >> 2;
    const int tg   = lane & 3;
    const int wm   = (wid & 1) * 64;
    const int wn   = (wid >> 1) * 32;

    if (tid < 128) {
        int m = m0 + tid;
        rows_sh[tid] = (m < cnt) ? g_pairs[e * TOKENS + m] : -1;
    }
    __syncthreads();

    const size_t eoff = (size_t)e * INTER * HIDDEN;
    const int kc = (tid & 7) * 4;

    const uint32_t* asrc[4];
    int  asz[4];
    uint32_t adst[4];
#pragma unroll
    for (int i = 0; i < 4; i++) {
        int m  = (tid >> 3) + 32 * i;
        int pr = rows_sh[m];
        asz[i]  = (pr >= 0) ? 16 : 0;
        asrc[i] = g_hbuf + (size_t)((pr >= 0) ? pr : 0) * INTER + kc;
        adst[i] = (uint32_t)(m * LDA + kc) * 4;
    }
    const uint32_t* bsrc[4];
    uint32_t bdst[4];
#pragma unroll
    for (int i = 0; i < 4; i++) {
        int r   = (tid >> 3) + 32 * i;
        int nn  = n0 + r;
        bsrc[i] = g_wd_t + eoff + (size_t)nn * INTER + kc;
        bdst[i] = (uint32_t)(r * LDA + kc) * 4;
    }

    float acc[4][4][4];
#pragma unroll
    for (int i = 0; i < 4; i++)
#pragma unroll
        for (int j = 0; j < 4; j++)
#pragma unroll
            for (int c = 0; c < 4; c++) acc[i][j][c] = 0.f;

#pragma unroll
    for (int s = 0; s < STAGES - 1; s++) {
        uint32_t ab = sb + (128 + s * 2 * TILE_U32) * 4;
        uint32_t bb = ab + TILE_U32 * 4;
        size_t ko = (size_t)s * KT;
#pragma unroll
        for (int i = 0; i < 4; i++) cp16(ab + adst[i], asrc[i] + ko, asz[i]);
#pragma unroll
        for (int i = 0; i < 4; i++) cp16(bb + bdst[i], bsrc[i] + ko, 16);
        CP_COMMIT();
    }

    const int NT = INTER / KT;   // 44
    int rd = 0;
    int wr = STAGES - 1;
    for (int kt = 0; kt < NT; kt++) {
        CP_WAIT1();
        __syncthreads();

        if (kt + STAGES - 1 < NT) {
            uint32_t ab = sb + (128 + wr * 2 * TILE_U32) * 4;
            uint32_t bb = ab + TILE_U32 * 4;
            size_t ko = (size_t)(kt + STAGES - 1) * KT;
#pragma unroll
            for (int i = 0; i < 4; i++) cp16(ab + adst[i], asrc[i] + ko, asz[i]);
#pragma unroll
            for (int i = 0; i < 4; i++) cp16(bb + bdst[i], bsrc[i] + ko, 16);
        }
        CP_COMMIT();

        const uint32_t* As = dsm + 128 + rd * 2 * TILE_U32;
        const uint32_t* Bs = As + TILE_U32;
#pragma unroll
        for (int ks = 0; ks < 4; ks++) {
            const int k = ks * 8;
            uint32_t a[4][4];
#pragma unroll
            for (int mi = 0; mi < 4; mi++) {
                int r = wm + mi * 16 + gr;
                a[mi][0] = As[r * LDA + k + tg];
                a[mi][1] = As[(r + 8) * LDA + k + tg];
                a[mi][2] = As[r * LDA + k + tg + 4];
                a[mi][3] = As[(r + 8) * LDA + k + tg + 4];
            }
            uint32_t b[4][2];
#pragma unroll
            for (int nj = 0; nj < 4; nj++) {
                int r = wn + nj * 8 + gr;
                b[nj][0] = Bs[r * LDA + k + tg];
                b[nj][1] = Bs[r * LDA + k + tg + 4];
            }
#pragma unroll
            for (int mi = 0; mi < 4; mi++)
#pragma unroll
                for (int nj = 0; nj < 4; nj++)
                    mma_tf32(acc[mi][nj], a[mi], b[nj]);
        }
        rd = (rd == STAGES - 1) ? 0 : rd + 1;
        wr = (wr == STAGES - 1) ? 0 : wr + 1;
    }

    const int colbase = n0 + wn + 2 * tg;
#pragma unroll
    for (int mi = 0; mi < 4; mi++) {
#pragma unroll
        for (int half = 0; half < 2; half++) {
            int row = wm + mi * 16 + gr + half * 8;
            int pr  = rows_sh[row];
            if (pr < 0) continue;
            float* yrow = g_ybuf + (size_t)pr * HIDDEN;
#pragma unroll
            for (int nj = 0; nj < 4; nj++) {
                float v0 = acc[mi][nj][half * 2 + 0];
                float v1 = acc[mi][nj][half * 2 + 1];
                *(float2*)&yrow[colbase + nj * 8] = make_float2(v0, v1);
            }
        }
    }
}

// ---------------- kernel 4: combine slots ----------------
__global__ __launch_bounds__(256) void combine_kernel(float* __restrict__ out)
{
    size_t idx = (size_t)blockIdx.x * blockDim.x + threadIdx.x;
    size_t total = (size_t)TOKENS * HIDDEN / 4;
    if (idx >= total) return;
    size_t t = idx / (HIDDEN / 4);
    size_t c = idx % (HIDDEN / 4);
    const float4* y0 = (const float4*)(g_ybuf + (size_t)(t * 2)     * HIDDEN) + c;
    const float4* y1 = (const float4*)(g_ybuf + (size_t)(t * 2 + 1) * HIDDEN) + c;
    float4 a = *y0, b = *y1;
    ((float4*)out)[idx] = make_float4(a.x + b.x, a.y + b.y, a.z + b.z, a.w + b.w);
}

// ---------------- launch ----------------
extern "C" void kernel_launch(void* const* d_in, const int* in_sizes, int n_in,
                              void* d_out, int out_size)
{
    const float* x  = (const float*)d_in[0];
    const float* wr = (const float*)d_in[1];
    const float* wg = (const float*)d_in[2];
    const float* wu = (const float*)d_in[3];
    const float* wd = (const float*)d_in[4];
    float* out = (float*)d_out;

    cudaFuncSetAttribute(gateup_kernel, cudaFuncAttributeMaxDynamicSharedMemorySize, SMEM_BYTES);
    cudaFuncSetAttribute(down_kernel,  cudaFuncAttributeMaxDynamicSharedMemorySize, SMEM_BYTES);

    zero_counts_kernel<<<1, 32>>>();
    router_kernel<<<TOKENS, 256>>>(x, wr);

    // preprocessing: tf32 conversion + weight transpose to [e][n][k]
    cvt_x_kernel<<<(TOKENS * HIDDEN) / (256 * 4), 256>>>(x);
    transpose_cvt_kernel<<<dim3(INTER / 32, HIDDEN / 32, NEXP), 256>>>(wg, 0, HIDDEN, INTER);
    transpose_cvt_kernel<<<dim3(INTER / 32, HIDDEN / 32, NEXP), 256>>>(wu, 1, HIDDEN, INTER);
    transpose_cvt_kernel<<<dim3(HIDDEN / 32, INTER / 32, NEXP), 256>>>(wd, 2, INTER, HIDDEN);

    dim3 g1(INTER / 64, TOKENS / 128, NEXP);    // 22 x 16 x 8
    gateup_kernel<<<g1, 256, SMEM_BYTES>>>();

    dim3 g2(HIDDEN / 128, TOKENS / 128, NEXP);  // 16 x 16 x 8
    down_kernel<<<g2, 256, SMEM_BYTES>>>();

    size_t total4 = (size_t)TOKENS * HIDDEN / 4;
    combine_kernel<<<(unsigned)((total4 + 255) / 256), 256>>>(out);
}

// round 8
// speedup vs baseline: 2.3634x; 1.0405x over previous
#include <cuda_runtime.h>
#include <cstdint>
#include <math.h>

#define TOKENS 2048
#define HIDDEN 2048
#define INTER  1408
#define NEXP   8
#define KT     32
#define LDA    36   // 32 + 4 pad (uint32): conflict-free ldmatrix row addressing
#define STAGES 3

// tiles: A = 64 x KT, B = 128 x KT (u32 elements)
#define AT (64 * LDA)
#define BT (128 * LDA)
#define STAGE_U32 (AT + BT)
#define SMEM_U32 (128 + STAGES * STAGE_U32)
#define SMEM_BYTES (SMEM_U32 * 4)

// ---------------- device scratch (no allocation) ----------------
__device__ int      g_counts[NEXP];
__device__ int      g_pairs[NEXP * TOKENS];               // encoded (t<<1)|slot
__device__ float    g_wts[TOKENS * 2];                    // combine weight per (t,slot)
__device__ uint32_t g_x_tf[(size_t)TOKENS * HIDDEN];      // x converted to tf32
__device__ uint32_t g_wg_t[(size_t)NEXP * HIDDEN * INTER]; // w_gate tf32, [e][n][k]
__device__ uint32_t g_wu_t[(size_t)NEXP * HIDDEN * INTER]; // w_up   tf32, [e][n][k]
__device__ uint32_t g_wd_t[(size_t)NEXP * INTER * HIDDEN]; // w_down tf32, [e][n][k]
__device__ uint32_t g_hbuf[(size_t)TOKENS * 2 * INTER];   // gated intermediate (tf32)
__device__ float    g_ybuf[(size_t)TOKENS * 2 * HIDDEN];  // down-proj per (t,slot)

__device__ __forceinline__ uint32_t f2tf32(float f) {
    uint32_t u;
    asm("cvt.rna.tf32.f32 %0, %1;" : "=r"(u) : "f"(f));
    return u;
}

// m16n8k8 tf32 MMA (standard PTX, sm_80+)
__device__ __forceinline__ void mma_tf32(float* c, const uint32_t* a, const uint32_t* b) {
    asm volatile(
        "mma.sync.aligned.m16n8k8.row.col.f32.tf32.tf32.f32 "
        "{%0,%1,%2,%3}, {%4,%5,%6,%7}, {%8,%9}, {%0,%1,%2,%3};"
        : "+f"(c[0]), "+f"(c[1]), "+f"(c[2]), "+f"(c[3])
        : "r"(a[0]), "r"(a[1]), "r"(a[2]), "r"(a[3]), "r"(b[0]), "r"(b[1]));
}

// ldmatrix x4: 4 8x4-u32 matrices; lane L supplies row addr of matrix L>>3
__device__ __forceinline__ void ldsm4(uint32_t* r, uint32_t addr) {
    asm volatile("ldmatrix.sync.aligned.m8n8.x4.shared.b16 {%0,%1,%2,%3}, [%4];"
        : "=r"(r[0]), "=r"(r[1]), "=r"(r[2]), "=r"(r[3]) : "r"(addr));
}

__device__ __forceinline__ void cp16(uint32_t dst, const void* src, int sz) {
    asm volatile("cp.async.cg.shared.global [%0], [%1], 16, %2;"
                 :: "r"(dst), "l"(src), "r"(sz) : "memory");
}
#define CP_COMMIT() asm volatile("cp.async.commit_group;" ::: "memory")
#define CP_WAIT1()  asm volatile("cp.async.wait_group 1;" ::: "memory")

// ---------------- kernel 0: zero counters ----------------
__global__ void zero_counts_kernel() {
    if (threadIdx.x < NEXP) g_counts[threadIdx.x] = 0;
}

// ---------------- preprocessing: transpose+convert weights (vectorized) ----------------
// src [e][K][N] (n contiguous) -> dst [e][N][K] (k contiguous), tf32 bits.
__global__ __launch_bounds__(256) void transpose_cvt_kernel(
    const float* __restrict__ src, int which, int K, int N)
{
    uint32_t* dst = (which == 0) ? g_wg_t : (which == 1) ? g_wu_t : g_wd_t;
    __shared__ uint32_t tile[32][33];
    const size_t eoff = (size_t)blockIdx.z * K * N;
    const int n0 = blockIdx.x * 32;
    const int k0 = blockIdx.y * 32;
    const int t  = threadIdx.x;

    // load: thread t reads float4 at (k row t>>3, n col (t&7)*4)
    {
        int kr  = t >> 3;
        int nc4 = (t & 7) * 4;
        float4 v = *(const float4*)(src + eoff + (size_t)(k0 + kr) * N + n0 + nc4);
        tile[kr][nc4 + 0] = f2tf32(v.x);
        tile[kr][nc4 + 1] = f2tf32(v.y);
        tile[kr][nc4 + 2] = f2tf32(v.z);
        tile[kr][nc4 + 3] = f2tf32(v.w);
    }
    __syncthreads();
    // store: thread t writes uint4 at (n row t>>3, k col (t&7)*4)
    {
        int nr  = t >> 3;
        int kc4 = (t & 7) * 4;
        uint4 o = make_uint4(tile[kc4 + 0][nr], tile[kc4 + 1][nr],
                             tile[kc4 + 2][nr], tile[kc4 + 3][nr]);
        *(uint4*)(dst + eoff + (size_t)(n0 + nr) * K + k0 + kc4) = o;
    }
}

// x -> tf32 (layout unchanged)
__global__ __launch_bounds__(256) void cvt_x_kernel(const float* __restrict__ src)
{
    size_t i = ((size_t)blockIdx.x * blockDim.x + threadIdx.x) * 4;
    float4 v = *(const float4*)(src + i);
    uint4 o = make_uint4(f2tf32(v.x), f2tf32(v.y), f2tf32(v.z), f2tf32(v.w));
    *(uint4*)(g_x_tf + i) = o;
}

// ---------------- kernel 1: router ----------------
__global__ __launch_bounds__(256) void router_kernel(
    const float* __restrict__ x, const float* __restrict__ wr)
{
    int t = blockIdx.x;
    __shared__ float red[256][NEXP];
    float acc[NEXP];
#pragma unroll
    for (int e = 0; e < NEXP; e++) acc[e] = 0.f;
    const float* xr = x + (size_t)t * HIDDEN;
    for (int h = threadIdx.x; h < HIDDEN; h += 256) {
        float xv = xr[h];
        const float* w = wr + (size_t)h * NEXP;
#pragma unroll
        for (int e = 0; e < NEXP; e++) acc[e] += xv * w[e];
    }
#pragma unroll
    for (int e = 0; e < NEXP; e++) red[threadIdx.x][e] = acc[e];
    __syncthreads();
    for (int s = 128; s > 0; s >>= 1) {
        if (threadIdx.x < s) {
#pragma unroll
            for (int e = 0; e < NEXP; e++)
                red[threadIdx.x][e] += red[threadIdx.x + s][e];
        }
        __syncthreads();
    }
    if (threadIdx.x == 0) {
        float l[NEXP];
#pragma unroll
        for (int e = 0; e < NEXP; e++) l[e] = red[0][e];
        int i0 = 0;
#pragma unroll
        for (int e = 1; e < NEXP; e++) if (l[e] > l[i0]) i0 = e;
        int i1 = -1;
#pragma unroll
        for (int e = 0; e < NEXP; e++) {
            if (e == i0) continue;
            if (i1 < 0 || l[e] > l[i1]) i1 = e;
        }
        float w0 = 1.f / (1.f + __expf(l[i1] - l[i0]));
        float w1 = 1.f - w0;
        int p0 = atomicAdd(&g_counts[i0], 1);
        g_pairs[i0 * TOKENS + p0] = (t << 1);
        int p1 = atomicAdd(&g_counts[i1], 1);
        g_pairs[i1 * TOKENS + p1] = (t << 1) | 1;
        g_wts[(t << 1)]     = w0;
        g_wts[(t << 1) | 1] = w1;
    }
}

// ---------------- kernel 2: grouped gate+up GEMM (64m x 64n, ldmatrix) ----------------
__global__ __launch_bounds__(256, 2) void gateup_kernel()
{
    const int e   = blockIdx.z;
    const int cnt = g_counts[e];
    const int m0  = blockIdx.y * 64;
    if (m0 >= cnt) return;
    const int n0  = blockIdx.x * 64;

    extern __shared__ __align__(16) uint32_t dsm[];
    int* rows_sh = (int*)dsm;
    const uint32_t sb = (uint32_t)__cvta_generic_to_shared(dsm);

    const int tid  = threadIdx.x;
    const int wid  = tid >> 5;
    const int lane = tid & 31;
    const int gr   = lane >> 2;
    const int tg   = lane & 3;
    const int wm   = (wid & 1) * 32;   // warp m offset (2 x 32)
    const int wn   = (wid >> 1) * 32;  // warp B-row offset (4 x 32)

    if (tid < 64) {
        int m = m0 + tid;
        rows_sh[tid] = (m < cnt) ? g_pairs[e * TOKENS + m] : -1;
    }
    __syncthreads();

    const size_t eoff = (size_t)e * HIDDEN * INTER;
    const int kc = (tid & 7) * 4;

    // staging: A 2 chunks, B 4 chunks of 16B per thread
    const uint32_t* asrc[2];
    int  asz[2];
    uint32_t adst[2];
#pragma unroll
    for (int i = 0; i < 2; i++) {
        int m  = (tid >> 3) + 32 * i;
        int pr = rows_sh[m];
        asz[i]  = (pr >= 0) ? 16 : 0;
        asrc[i] = g_x_tf + (size_t)((pr >= 0) ? (pr >> 1) : 0) * HIDDEN + kc;
        adst[i] = (uint32_t)(m * LDA + kc) * 4;
    }
    const uint32_t* bsrc[4];
    uint32_t bdst[4];
#pragma unroll
    for (int i = 0; i < 4; i++) {
        int r    = (tid >> 3) + 32 * i;      // B tile row 0..127
        int half = (r >> 4) & 1;             // 0 gate / 1 up (16-row granularity)
        int nn   = n0 + (r >> 5) * 16 + (r & 15);
        bsrc[i]  = (half ? g_wu_t : g_wg_t) + eoff + (size_t)nn * HIDDEN + kc;
        bdst[i]  = (uint32_t)(r * LDA + kc) * 4;
    }

    // ldmatrix lane constants
    const int q       = lane >> 3;
    const int a_row_l = wm + (q & 1) * 8 + (lane & 7);
    const int a_col_l = (q >> 1) * 4;
    const int b_row_l = wn + ((lane >> 4) << 3) + (lane & 7);
    const int b_col_l = ((lane >> 3) & 1) * 4;

    float acc[2][4][4];
#pragma unroll
    for (int i = 0; i < 2; i++)
#pragma unroll
        for (int j = 0; j < 4; j++)
#pragma unroll
            for (int c = 0; c < 4; c++) acc[i][j][c] = 0.f;

    // prologue: stage tiles 0..STAGES-2
#pragma unroll
    for (int s = 0; s < STAGES - 1; s++) {
        uint32_t ab = sb + (128 + s * STAGE_U32) * 4;
        uint32_t bb = ab + AT * 4;
        size_t ko = (size_t)s * KT;
#pragma unroll
        for (int i = 0; i < 2; i++) cp16(ab + adst[i], asrc[i] + ko, asz[i]);
#pragma unroll
        for (int i = 0; i < 4; i++) cp16(bb + bdst[i], bsrc[i] + ko, 16);
        CP_COMMIT();
    }

    const int NT = HIDDEN / KT;   // 64
    int rd = 0, wr = STAGES - 1;
    for (int kt = 0; kt < NT; kt++) {
        CP_WAIT1();
        __syncthreads();

        if (kt + STAGES - 1 < NT) {
            uint32_t ab = sb + (128 + wr * STAGE_U32) * 4;
            uint32_t bb = ab + AT * 4;
            size_t ko = (size_t)(kt + STAGES - 1) * KT;
#pragma unroll
            for (int i = 0; i < 2; i++) cp16(ab + adst[i], asrc[i] + ko, asz[i]);
#pragma unroll
            for (int i = 0; i < 4; i++) cp16(bb + bdst[i], bsrc[i] + ko, 16);
        }
        CP_COMMIT();

        const uint32_t Ab = sb + (128 + rd * STAGE_U32) * 4;
        const uint32_t Bb = Ab + AT * 4;
#pragma unroll
        for (int ks = 0; ks < 4; ks++) {
            const int k = ks * 8;
            uint32_t a[2][4];
#pragma unroll
            for (int mi = 0; mi < 2; mi++)
                ldsm4(a[mi], Ab + (uint32_t)(((a_row_l + mi * 16) * LDA) + k + a_col_l) * 4);
            uint32_t b0[4], b1[4];
            ldsm4(b0, Bb + (uint32_t)((b_row_l * LDA) + k + b_col_l) * 4);
            ldsm4(b1, Bb + (uint32_t)(((b_row_l + 16) * LDA) + k + b_col_l) * 4);
#pragma unroll
            for (int mi = 0; mi < 2; mi++) {
                mma_tf32(acc[mi][0], a[mi], &b0[0]);
                mma_tf32(acc[mi][1], a[mi], &b0[2]);
                mma_tf32(acc[mi][2], a[mi], &b1[0]);
                mma_tf32(acc[mi][3], a[mi], &b1[2]);
            }
        }
        rd = (rd == STAGES - 1) ? 0 : rd + 1;
        wr = (wr == STAGES - 1) ? 0 : wr + 1;
    }

    // epilogue: nj 0,1 = gate, nj 2,3 = up at same output cols
    const int colbase = n0 + (wid >> 1) * 16 + 2 * tg;
#pragma unroll
    for (int mi = 0; mi < 2; mi++) {
#pragma unroll
        for (int half = 0; half < 2; half++) {
            int row = wm + mi * 16 + gr + half * 8;
            int pr  = rows_sh[row];
            if (pr < 0) continue;
            float wt = g_wts[pr];
            uint32_t* hrow = g_hbuf + (size_t)pr * INTER;
#pragma unroll
            for (int nj = 0; nj < 2; nj++) {
                float g0 = acc[mi][nj][half * 2 + 0];
                float g1 = acc[mi][nj][half * 2 + 1];
                float u0 = acc[mi][nj + 2][half * 2 + 0];
                float u1 = acc[mi][nj + 2][half * 2 + 1];
                float h0 = (g0 / (1.f + __expf(-g0))) * u0 * wt;
                float h1 = (g1 / (1.f + __expf(-g1))) * u1 * wt;
                uint2 o = make_uint2(f2tf32(h0), f2tf32(h1));
                *(uint2*)&hrow[colbase + nj * 8] = o;
            }
        }
    }
}

// ---------------- kernel 3: grouped down GEMM (64m x 128n, ldmatrix) ----------------
__global__ __launch_bounds__(256, 2) void down_kernel()
{
    const int e   = blockIdx.z;
    const int cnt = g_counts[e];
    const int m0  = blockIdx.y * 64;
    if (m0 >= cnt) return;
    const int n0  = blockIdx.x * 128;

    extern __shared__ __align__(16) uint32_t dsm[];
    int* rows_sh = (int*)dsm;
    const uint32_t sb = (uint32_t)__cvta_generic_to_shared(dsm);

    const int tid  = threadIdx.x;
    const int wid  = tid >> 5;
    const int lane = tid & 31;
    const int gr   = lane >> 2;
    const int tg   = lane & 3;
    const int wm   = (wid & 1) * 32;
    const int wn   = (wid >> 1) * 32;

    if (tid < 64) {
        int m = m0 + tid;
        rows_sh[tid] = (m < cnt) ? g_pairs[e * TOKENS + m] : -1;
    }
    __syncthreads();

    const size_t eoff = (size_t)e * INTER * HIDDEN;
    const int kc = (tid & 7) * 4;

    const uint32_t* asrc[2];
    int  asz[2];
    uint32_t adst[2];
#pragma unroll
    for (int i = 0; i < 2; i++) {
        int m  = (tid >> 3) + 32 * i;
        int pr = rows_sh[m];
        asz[i]  = (pr >= 0) ? 16 : 0;
        asrc[i] = g_hbuf + (size_t)((pr >= 0) ? pr : 0) * INTER + kc;
        adst[i] = (uint32_t)(m * LDA + kc) * 4;
    }
    const uint32_t* bsrc[4];
    uint32_t bdst[4];
#pragma unroll
    for (int i = 0; i < 4; i++) {
        int r   = (tid >> 3) + 32 * i;
        bsrc[i] = g_wd_t + eoff + (size_t)(n0 + r) * INTER + kc;
        bdst[i] = (uint32_t)(r * LDA + kc) * 4;
    }

    const int q       = lane >> 3;
    const int a_row_l = wm + (q & 1) * 8 + (lane & 7);
    const int a_col_l = (q >> 1) * 4;
    const int b_row_l = wn + ((lane >> 4) << 3) + (lane & 7);
    const int b_col_l = ((lane >> 3) & 1) * 4;

    float acc[2][4][4];
#pragma unroll
    for (int i = 0; i < 2; i++)
#pragma unroll
        for (int j = 0; j < 4; j++)
#pragma unroll
            for (int c = 0; c < 4; c++) acc[i][j][c] = 0.f;

#pragma unroll
    for (int s = 0; s < STAGES - 1; s++) {
        uint32_t ab = sb + (128 + s * STAGE_U32) * 4;
        uint32_t bb = ab + AT * 4;
        size_t ko = (size_t)s * KT;
#pragma unroll
        for (int i = 0; i < 2; i++) cp16(ab + adst[i], asrc[i] + ko, asz[i]);
#pragma unroll
        for (int i = 0; i < 4; i++) cp16(bb + bdst[i], bsrc[i] + ko, 16);
        CP_COMMIT();
    }

    const int NT = INTER / KT;   // 44
    int rd = 0, wr = STAGES - 1;
    for (int kt = 0; kt < NT; kt++) {
        CP_WAIT1();
        __syncthreads();

        if (kt + STAGES - 1 < NT) {
            uint32_t ab = sb + (128 + wr * STAGE_U32) * 4;
            uint32_t bb = ab + AT * 4;
            size_t ko = (size_t)(kt + STAGES - 1) * KT;
#pragma unroll
            for (int i = 0; i < 2; i++) cp16(ab + adst[i], asrc[i] + ko, asz[i]);
#pragma unroll
            for (int i = 0; i < 4; i++) cp16(bb + bdst[i], bsrc[i] + ko, 16);
        }
        CP_COMMIT();

        const uint32_t Ab = sb + (128 + rd * STAGE_U32) * 4;
        const uint32_t Bb = Ab + AT * 4;
#pragma unroll
        for (int ks = 0; ks < 4; ks++) {
            const int k = ks * 8;
            uint32_t a[2][4];
#pragma unroll
            for (int mi = 0; mi < 2; mi++)
                ldsm4(a[mi], Ab + (uint32_t)(((a_row_l + mi * 16) * LDA) + k + a_col_l) * 4);
            uint32_t b0[4], b1[4];
            ldsm4(b0, Bb + (uint32_t)((b_row_l * LDA) + k + b_col_l) * 4);
            ldsm4(b1, Bb + (uint32_t)(((b_row_l + 16) * LDA) + k + b_col_l) * 4);
#pragma unroll
            for (int mi = 0; mi < 2; mi++) {
                mma_tf32(acc[mi][0], a[mi], &b0[0]);
                mma_tf32(acc[mi][1], a[mi], &b0[2]);
                mma_tf32(acc[mi][2], a[mi], &b1[0]);
                mma_tf32(acc[mi][3], a[mi], &b1[2]);
            }
        }
        rd = (rd == STAGES - 1) ? 0 : rd + 1;
        wr = (wr == STAGES - 1) ? 0 : wr + 1;
    }

    const int colbase = n0 + wn + 2 * tg;
#pragma unroll
    for (int mi = 0; mi < 2; mi++) {
#pragma unroll
        for (int half = 0; half < 2; half++) {
            int row = wm + mi * 16 + gr + half * 8;
            int pr  = rows_sh[row];
            if (pr < 0) continue;
            float* yrow = g_ybuf + (size_t)pr * HIDDEN;
#pragma unroll
            for (int nj = 0; nj < 4; nj++) {
                float v0 = acc[mi][nj][half * 2 + 0];
                float v1 = acc[mi][nj][half * 2 + 1];
                *(float2*)&yrow[colbase + nj * 8] = make_float2(v0, v1);
            }
        }
    }
}

// ---------------- kernel 4: combine slots ----------------
__global__ __launch_bounds__(256) void combine_kernel(float* __restrict__ out)
{
    size_t idx = (size_t)blockIdx.x * blockDim.x + threadIdx.x;
    size_t total = (size_t)TOKENS * HIDDEN / 4;
    if (idx >= total) return;
    size_t t = idx / (HIDDEN / 4);
    size_t c = idx % (HIDDEN / 4);
    const float4* y0 = (const float4*)(g_ybuf + (size_t)(t * 2)     * HIDDEN) + c;
    const float4* y1 = (const float4*)(g_ybuf + (size_t)(t * 2 + 1) * HIDDEN) + c;
    float4 a = *y0, b = *y1;
    ((float4*)out)[idx] = make_float4(a.x + b.x, a.y + b.y, a.z + b.z, a.w + b.w);
}

// ---------------- launch ----------------
extern "C" void kernel_launch(void* const* d_in, const int* in_sizes, int n_in,
                              void* d_out, int out_size)
{
    const float* x  = (const float*)d_in[0];
    const float* wr = (const float*)d_in[1];
    const float* wg = (const float*)d_in[2];
    const float* wu = (const float*)d_in[3];
    const float* wd = (const float*)d_in[4];
    float* out = (float*)d_out;

    cudaFuncSetAttribute(gateup_kernel, cudaFuncAttributeMaxDynamicSharedMemorySize, SMEM_BYTES);
    cudaFuncSetAttribute(down_kernel,  cudaFuncAttributeMaxDynamicSharedMemorySize, SMEM_BYTES);

    zero_counts_kernel<<<1, 32>>>();
    router_kernel<<<TOKENS, 256>>>(x, wr);

    // preprocessing: tf32 conversion + weight transpose to [e][n][k]
    cvt_x_kernel<<<(TOKENS * HIDDEN) / (256 * 4), 256>>>(x);
    transpose_cvt_kernel<<<dim3(INTER / 32, HIDDEN / 32, NEXP), 256>>>(wg, 0, HIDDEN, INTER);
    transpose_cvt_kernel<<<dim3(INTER / 32, HIDDEN / 32, NEXP), 256>>>(wu, 1, HIDDEN, INTER);
    transpose_cvt_kernel<<<dim3(HIDDEN / 32, INTER / 32, NEXP), 256>>>(wd, 2, INTER, HIDDEN);

    dim3 g1(INTER / 64, TOKENS / 64, NEXP);     // 22 x 32 x 8 (most m-tiles exit early)
    gateup_kernel<<<g1, 256, SMEM_BYTES>>>();

    dim3 g2(HIDDEN / 128, TOKENS / 64, NEXP);   // 16 x 32 x 8
    down_kernel<<<g2, 256, SMEM_BYTES>>>();

    size_t total4 = (size_t)TOKENS * HIDDEN / 4;
    combine_kernel<<<(unsigned)((total4 + 255) / 256), 256>>>(out);
}

// round 9
// speedup vs baseline: 3.6072x; 1.5263x over previous
#include <cuda_runtime.h>
#include <cuda_fp16.h>
#include <cstdint>
#include <math.h>

#define TOKENS 2048
#define HIDDEN 2048
#define INTER  1408
#define NEXP   8
#define KTH    64          // k elements per tile (halfs) = 128B rows
#define LDAH   72          // padded row stride in halfs (144B): conflict-free ldmatrix
#define STAGES 3

#define AT_B    (64  * LDAH * 2)   // A tile bytes  (9216)
#define BT_B    (128 * LDAH * 2)   // B tile bytes  (18432)
#define STAGE_B (AT_B + BT_B)      // 27648
#define SMEM_BYTES (256 + STAGES * STAGE_B)   // 83200

// ---------------- device scratch (no allocation) ----------------
__device__ int    g_counts[NEXP];
__device__ int    g_pairs[NEXP * TOKENS];                 // encoded (t<<1)|slot
__device__ float  g_wts[TOKENS * 2];                      // combine weight per (t,slot)
__device__ __half g_x_h[(size_t)TOKENS * HIDDEN];         // x in fp16
__device__ __half g_wg_h[(size_t)NEXP * HIDDEN * INTER];  // w_gate fp16, [e][n][k]
__device__ __half g_wu_h[(size_t)NEXP * HIDDEN * INTER];  // w_up   fp16, [e][n][k]
__device__ __half g_wd_h[(size_t)NEXP * INTER * HIDDEN];  // w_down fp16, [e][n][k]
__device__ __half g_hbuf_h[(size_t)TOKENS * 2 * INTER];   // gated intermediate fp16
__device__ float  g_ybuf[(size_t)TOKENS * 2 * HIDDEN];    // down-proj per (t,slot)

// m16n8k16 fp16 MMA, fp32 accumulate (standard PTX, sm_80+)
__device__ __forceinline__ void mma_f16(float* c, const uint32_t* a,
                                        uint32_t b0, uint32_t b1) {
    asm volatile(
        "mma.sync.aligned.m16n8k16.row.col.f32.f16.f16.f32 "
        "{%0,%1,%2,%3}, {%4,%5,%6,%7}, {%8,%9}, {%0,%1,%2,%3};"
        : "+f"(c[0]), "+f"(c[1]), "+f"(c[2]), "+f"(c[3])
        : "r"(a[0]), "r"(a[1]), "r"(a[2]), "r"(a[3]), "r"(b0), "r"(b1));
}

// ldmatrix x4 (b16): 4 8x8 fp16 matrices
__device__ __forceinline__ void ldsm4(uint32_t* r, uint32_t addr) {
    asm volatile("ldmatrix.sync.aligned.m8n8.x4.shared.b16 {%0,%1,%2,%3}, [%4];"
        : "=r"(r[0]), "=r"(r[1]), "=r"(r[2]), "=r"(r[3]) : "r"(addr));
}

__device__ __forceinline__ void cp16(uint32_t dst, const void* src, int sz) {
    asm volatile("cp.async.cg.shared.global [%0], [%1], 16, %2;"
                 :: "r"(dst), "l"(src), "r"(sz) : "memory");
}
#define CP_COMMIT() asm volatile("cp.async.commit_group;" ::: "memory")
#define CP_WAIT1()  asm volatile("cp.async.wait_group 1;" ::: "memory")

__device__ __forceinline__ uint32_t hpack(float a, float b) {
    __half2 h = __floats2half2_rn(a, b);
    return *(uint32_t*)&h;
}

// ---------------- kernel 0: zero counters ----------------
__global__ void zero_counts_kernel() {
    if (threadIdx.x < NEXP) g_counts[threadIdx.x] = 0;
}

// ---------------- preprocessing: transpose+convert weights to fp16 ----------------
// src [e][K][N] (n contiguous, fp32) -> dst [e][N][K] (k contiguous, fp16)
__global__ __launch_bounds__(256) void transpose_cvt_kernel(
    const float* __restrict__ src, int which, int K, int N)
{
    __half* dst = (which == 0) ? g_wg_h : (which == 1) ? g_wu_h : g_wd_h;
    __shared__ uint32_t tile[32][33];   // one fp16 value per slot (low 16 bits)
    const size_t eoff = (size_t)blockIdx.z * K * N;
    const int n0 = blockIdx.x * 32;
    const int k0 = blockIdx.y * 32;
    const int t  = threadIdx.x;
    {
        int kr  = t >> 3;
        int nc4 = (t & 7) * 4;
        float4 v = *(const float4*)(src + eoff + (size_t)(k0 + kr) * N + n0 + nc4);
        tile[kr][nc4 + 0] = (uint32_t)__half_as_ushort(__float2half_rn(v.x));
        tile[kr][nc4 + 1] = (uint32_t)__half_as_ushort(__float2half_rn(v.y));
        tile[kr][nc4 + 2] = (uint32_t)__half_as_ushort(__float2half_rn(v.z));
        tile[kr][nc4 + 3] = (uint32_t)__half_as_ushort(__float2half_rn(v.w));
    }
    __syncthreads();
    {
        int nr  = t >> 3;
        int kc4 = (t & 7) * 4;
        uint2 o;
        o.x = tile[kc4 + 0][nr] | (tile[kc4 + 1][nr] << 16);
        o.y = tile[kc4 + 2][nr] | (tile[kc4 + 3][nr] << 16);
        *(uint2*)(dst + eoff + (size_t)(n0 + nr) * K + k0 + kc4) = o;
    }
}

// x -> fp16 (layout unchanged)
__global__ __launch_bounds__(256) void cvt_x_kernel(const float* __restrict__ src)
{
    size_t i = ((size_t)blockIdx.x * blockDim.x + threadIdx.x) * 4;
    float4 v = *(const float4*)(src + i);
    uint2 o;
    o.x = hpack(v.x, v.y);
    o.y = hpack(v.z, v.w);
    *(uint2*)(g_x_h + i) = o;
}

// ---------------- kernel 1: router ----------------
__global__ __launch_bounds__(256) void router_kernel(
    const float* __restrict__ x, const float* __restrict__ wr)
{
    int t = blockIdx.x;
    __shared__ float red[256][NEXP];
    float acc[NEXP];
#pragma unroll
    for (int e = 0; e < NEXP; e++) acc[e] = 0.f;
    const float* xr = x + (size_t)t * HIDDEN;
    for (int h = threadIdx.x; h < HIDDEN; h += 256) {
        float xv = xr[h];
        const float* w = wr + (size_t)h * NEXP;
#pragma unroll
        for (int e = 0; e < NEXP; e++) acc[e] += xv * w[e];
    }
#pragma unroll
    for (int e = 0; e < NEXP; e++) red[threadIdx.x][e] = acc[e];
    __syncthreads();
    for (int s = 128; s > 0; s >>= 1) {
        if (threadIdx.x < s) {
#pragma unroll
            for (int e = 0; e < NEXP; e++)
                red[threadIdx.x][e] += red[threadIdx.x + s][e];
        }
        __syncthreads();
    }
    if (threadIdx.x == 0) {
        float l[NEXP];
#pragma unroll
        for (int e = 0; e < NEXP; e++) l[e] = red[0][e];
        int i0 = 0;
#pragma unroll
        for (int e = 1; e < NEXP; e++) if (l[e] > l[i0]) i0 = e;
        int i1 = -1;
#pragma unroll
        for (int e = 0; e < NEXP; e++) {
            if (e == i0) continue;
            if (i1 < 0 || l[e] > l[i1]) i1 = e;
        }
        float w0 = 1.f / (1.f + __expf(l[i1] - l[i0]));
        float w1 = 1.f - w0;
        int p0 = atomicAdd(&g_counts[i0], 1);
        g_pairs[i0 * TOKENS + p0] = (t << 1);
        int p1 = atomicAdd(&g_counts[i1], 1);
        g_pairs[i1 * TOKENS + p1] = (t << 1) | 1;
        g_wts[(t << 1)]     = w0;
        g_wts[(t << 1) | 1] = w1;
    }
}

// ---------------- kernel 2: grouped gate+up GEMM (fp16, 64m x 64n) ----------------
__global__ __launch_bounds__(256, 2) void gateup_kernel()
{
    const int e   = blockIdx.z;
    const int cnt = g_counts[e];
    const int m0  = blockIdx.y * 64;
    if (m0 >= cnt) return;
    const int n0  = blockIdx.x * 64;

    extern __shared__ __align__(16) uint32_t dsm[];
    int* rows_sh = (int*)dsm;
    const uint32_t sb = (uint32_t)__cvta_generic_to_shared(dsm);

    const int tid  = threadIdx.x;
    const int wid  = tid >> 5;
    const int lane = tid & 31;
    const int gr   = lane >> 2;
    const int tg   = lane & 3;
    const int wm   = (wid & 1) * 32;   // warp m offset
    const int wn   = (wid >> 1) * 32;  // warp B-row offset

    if (tid < 64) {
        int m = m0 + tid;
        rows_sh[tid] = (m < cnt) ? g_pairs[e * TOKENS + m] : -1;
    }
    __syncthreads();

    const size_t eoff = (size_t)e * HIDDEN * INTER;

    // staging: A 2 chunks of 16B, B 4 chunks of 16B per thread (8 chunks/row)
    const __half* asrc[2];
    int  asz[2];
    uint32_t adst[2];   // byte offset within stage
#pragma unroll
    for (int i = 0; i < 2; i++) {
        int q  = tid + 256 * i;
        int m  = q >> 3;
        int c  = q & 7;
        int pr = rows_sh[m];
        asz[i]  = (pr >= 0) ? 16 : 0;
        asrc[i] = g_x_h + (size_t)((pr >= 0) ? (pr >> 1) : 0) * HIDDEN + c * 8;
        adst[i] = (uint32_t)(m * 144 + c * 16);
    }
    const __half* bsrc[4];
    uint32_t bdst[4];
#pragma unroll
    for (int i = 0; i < 4; i++) {
        int q    = tid + 256 * i;
        int r    = q >> 3;               // B tile row 0..127
        int c    = q & 7;
        int half = (r >> 4) & 1;         // 0 gate / 1 up (16-row granularity)
        int nn   = n0 + (r >> 5) * 16 + (r & 15);
        bsrc[i]  = (half ? g_wu_h : g_wg_h) + eoff + (size_t)nn * HIDDEN + c * 8;
        bdst[i]  = (uint32_t)(r * 144 + c * 16);
    }

    // ldmatrix lane constants: lanes 0-15 -> rows +0..15, lanes 16-31 -> k+8
    const int rlo  = lane & 15;
    const int kadd = (lane >> 4) * 8;

    float acc[2][4][4];
#pragma unroll
    for (int i = 0; i < 2; i++)
#pragma unroll
        for (int j = 0; j < 4; j++)
#pragma unroll
            for (int c = 0; c < 4; c++) acc[i][j][c] = 0.f;

    // prologue
#pragma unroll
    for (int s = 0; s < STAGES - 1; s++) {
        uint32_t ab = sb + 256 + s * STAGE_B;
        uint32_t bb = ab + AT_B;
        size_t ko = (size_t)s * KTH;
#pragma unroll
        for (int i = 0; i < 2; i++) cp16(ab + adst[i], asrc[i] + ko, asz[i]);
#pragma unroll
        for (int i = 0; i < 4; i++) cp16(bb + bdst[i], bsrc[i] + ko, 16);
        CP_COMMIT();
    }

    const int NT = HIDDEN / KTH;   // 32
    int rd = 0, wr = STAGES - 1;
    for (int kt = 0; kt < NT; kt++) {
        CP_WAIT1();
        __syncthreads();

        if (kt + STAGES - 1 < NT) {
            uint32_t ab = sb + 256 + wr * STAGE_B;
            uint32_t bb = ab + AT_B;
            size_t ko = (size_t)(kt + STAGES - 1) * KTH;
#pragma unroll
            for (int i = 0; i < 2; i++) cp16(ab + adst[i], asrc[i] + ko, asz[i]);
#pragma unroll
            for (int i = 0; i < 4; i++) cp16(bb + bdst[i], bsrc[i] + ko, 16);
        }
        CP_COMMIT();

        const uint32_t Ab = sb + 256 + rd * STAGE_B;
        const uint32_t Bb = Ab + AT_B;
#pragma unroll
        for (int ks = 0; ks < 4; ks++) {
            const int k = ks * 16;
            uint32_t a[2][4];
#pragma unroll
            for (int mi = 0; mi < 2; mi++)
                ldsm4(a[mi], Ab + (uint32_t)((wm + mi * 16 + rlo) * 144 + (k + kadd) * 2));
            uint32_t b0[4], b1[4];
            ldsm4(b0, Bb + (uint32_t)((wn + rlo)      * 144 + (k + kadd) * 2));
            ldsm4(b1, Bb + (uint32_t)((wn + 16 + rlo) * 144 + (k + kadd) * 2));
#pragma unroll
            for (int mi = 0; mi < 2; mi++) {
                mma_f16(acc[mi][0], a[mi], b0[0], b0[2]);
                mma_f16(acc[mi][1], a[mi], b0[1], b0[3]);
                mma_f16(acc[mi][2], a[mi], b1[0], b1[2]);
                mma_f16(acc[mi][3], a[mi], b1[1], b1[3]);
            }
        }
        rd = (rd == STAGES - 1) ? 0 : rd + 1;
        wr = (wr == STAGES - 1) ? 0 : wr + 1;
    }

    // epilogue: nj 0,1 = gate, nj 2,3 = up at same output cols; hbuf fp16
    const int colbase = n0 + (wid >> 1) * 16 + 2 * tg;
#pragma unroll
    for (int mi = 0; mi < 2; mi++) {
#pragma unroll
        for (int half = 0; half < 2; half++) {
            int row = wm + mi * 16 + gr + half * 8;
            int pr  = rows_sh[row];
            if (pr < 0) continue;
            float wt = g_wts[pr];
            __half* hrow = g_hbuf_h + (size_t)pr * INTER;
#pragma unroll
            for (int nj = 0; nj < 2; nj++) {
                float g0 = acc[mi][nj][half * 2 + 0];
                float g1 = acc[mi][nj][half * 2 + 1];
                float u0 = acc[mi][nj + 2][half * 2 + 0];
                float u1 = acc[mi][nj + 2][half * 2 + 1];
                float h0 = (g0 / (1.f + __expf(-g0))) * u0 * wt;
                float h1 = (g1 / (1.f + __expf(-g1))) * u1 * wt;
                *(uint32_t*)&hrow[colbase + nj * 8] = hpack(h0, h1);
            }
        }
    }
}

// ---------------- kernel 3: grouped down GEMM (fp16, 64m x 128n) ----------------
__global__ __launch_bounds__(256, 2) void down_kernel()
{
    const int e   = blockIdx.z;
    const int cnt = g_counts[e];
    const int m0  = blockIdx.y * 64;
    if (m0 >= cnt) return;
    const int n0  = blockIdx.x * 128;

    extern __shared__ __align__(16) uint32_t dsm[];
    int* rows_sh = (int*)dsm;
    const uint32_t sb = (uint32_t)__cvta_generic_to_shared(dsm);

    const int tid  = threadIdx.x;
    const int wid  = tid >> 5;
    const int lane = tid & 31;
    const int gr   = lane >> 2;
    const int tg   = lane & 3;
    const int wm   = (wid & 1) * 32;
    const int wn   = (wid >> 1) * 32;

    if (tid < 64) {
        int m = m0 + tid;
        rows_sh[tid] = (m < cnt) ? g_pairs[e * TOKENS + m] : -1;
    }
    __syncthreads();

    const size_t eoff = (size_t)e * HIDDEN * INTER;

    const __half* asrc[2];
    int  asz[2];
    uint32_t adst[2];
#pragma unroll
    for (int i = 0; i < 2; i++) {
        int q  = tid + 256 * i;
        int m  = q >> 3;
        int c  = q & 7;
        int pr = rows_sh[m];
        asz[i]  = (pr >= 0) ? 16 : 0;
        asrc[i] = g_hbuf_h + (size_t)((pr >= 0) ? pr : 0) * INTER + c * 8;
        adst[i] = (uint32_t)(m * 144 + c * 16);
    }
    const __half* bsrc[4];
    uint32_t bdst[4];
#pragma unroll
    for (int i = 0; i < 4; i++) {
        int q   = tid + 256 * i;
        int r   = q >> 3;
        int c   = q & 7;
        bsrc[i] = g_wd_h + eoff + (size_t)(n0 + r) * INTER + c * 8;
        bdst[i] = (uint32_t)(r * 144 + c * 16);
    }

    const int rlo  = lane & 15;
    const int kadd = (lane >> 4) * 8;

    float acc[2][4][4];
#pragma unroll
    for (int i = 0; i < 2; i++)
#pragma unroll
        for (int j = 0; j < 4; j++)
#pragma unroll
            for (int c = 0; c < 4; c++) acc[i][j][c] = 0.f;

#pragma unroll
    for (int s = 0; s < STAGES - 1; s++) {
        uint32_t ab = sb + 256 + s * STAGE_B;
        uint32_t bb = ab + AT_B;
        size_t ko = (size_t)s * KTH;
#pragma unroll
        for (int i = 0; i < 2; i++) cp16(ab + adst[i], asrc[i] + ko, asz[i]);
#pragma unroll
        for (int i = 0; i < 4; i++) cp16(bb + bdst[i], bsrc[i] + ko, 16);
        CP_COMMIT();
    }

    const int NT = INTER / KTH;   // 22
    int rd = 0, wr = STAGES - 1;
    for (int kt = 0; kt < NT; kt++) {
        CP_WAIT1();
        __syncthreads();

        if (kt + STAGES - 1 < NT) {
            uint32_t ab = sb + 256 + wr * STAGE_B;
            uint32_t bb = ab + AT_B;
            size_t ko = (size_t)(kt + STAGES - 1) * KTH;
#pragma unroll
            for (int i = 0; i < 2; i++) cp16(ab + adst[i], asrc[i] + ko, asz[i]);
#pragma unroll
            for (int i = 0; i < 4; i++) cp16(bb + bdst[i], bsrc[i] + ko, 16);
        }
        CP_COMMIT();

        const uint32_t Ab = sb + 256 + rd * STAGE_B;
        const uint32_t Bb = Ab + AT_B;
#pragma unroll
        for (int ks = 0; ks < 4; ks++) {
            const int k = ks * 16;
            uint32_t a[2][4];
#pragma unroll
            for (int mi = 0; mi < 2; mi++)
                ldsm4(a[mi], Ab + (uint32_t)((wm + mi * 16 + rlo) * 144 + (k + kadd) * 2));
            uint32_t b0[4], b1[4];
            ldsm4(b0, Bb + (uint32_t)((wn + rlo)      * 144 + (k + kadd) * 2));
            ldsm4(b1, Bb + (uint32_t)((wn + 16 + rlo) * 144 + (k + kadd) * 2));
#pragma unroll
            for (int mi = 0; mi < 2; mi++) {
                mma_f16(acc[mi][0], a[mi], b0[0], b0[2]);
                mma_f16(acc[mi][1], a[mi], b0[1], b0[3]);
                mma_f16(acc[mi][2], a[mi], b1[0], b1[2]);
                mma_f16(acc[mi][3], a[mi], b1[1], b1[3]);
            }
        }
        rd = (rd == STAGES - 1) ? 0 : rd + 1;
        wr = (wr == STAGES - 1) ? 0 : wr + 1;
    }

    const int colbase = n0 + wn + 2 * tg;
#pragma unroll
    for (int mi = 0; mi < 2; mi++) {
#pragma unroll
        for (int half = 0; half < 2; half++) {
            int row = wm + mi * 16 + gr + half * 8;
            int pr  = rows_sh[row];
            if (pr < 0) continue;
            float* yrow = g_ybuf + (size_t)pr * HIDDEN;
#pragma unroll
            for (int nj = 0; nj < 4; nj++) {
                float v0 = acc[mi][nj][half * 2 + 0];
                float v1 = acc[mi][nj][half * 2 + 1];
                *(float2*)&yrow[colbase + nj * 8] = make_float2(v0, v1);
            }
        }
    }
}

// ---------------- kernel 4: combine slots ----------------
__global__ __launch_bounds__(256) void combine_kernel(float* __restrict__ out)
{
    size_t idx = (size_t)blockIdx.x * blockDim.x + threadIdx.x;
    size_t total = (size_t)TOKENS * HIDDEN / 4;
    if (idx >= total) return;
    size_t t = idx / (HIDDEN / 4);
    size_t c = idx % (HIDDEN / 4);
    const float4* y0 = (const float4*)(g_ybuf + (size_t)(t * 2)     * HIDDEN) + c;
    const float4* y1 = (const float4*)(g_ybuf + (size_t)(t * 2 + 1) * HIDDEN) + c;
    float4 a = *y0, b = *y1;
    ((float4*)out)[idx] = make_float4(a.x + b.x, a.y + b.y, a.z + b.z, a.w + b.w);
}

// ---------------- launch ----------------
extern "C" void kernel_launch(void* const* d_in, const int* in_sizes, int n_in,
                              void* d_out, int out_size)
{
    const float* x  = (const float*)d_in[0];
    const float* wr = (const float*)d_in[1];
    const float* wg = (const float*)d_in[2];
    const float* wu = (const float*)d_in[3];
    const float* wd = (const float*)d_in[4];
    float* out = (float*)d_out;

    cudaFuncSetAttribute(gateup_kernel, cudaFuncAttributeMaxDynamicSharedMemorySize, SMEM_BYTES);
    cudaFuncSetAttribute(down_kernel,  cudaFuncAttributeMaxDynamicSharedMemorySize, SMEM_BYTES);

    zero_counts_kernel<<<1, 32>>>();
    router_kernel<<<TOKENS, 256>>>(x, wr);

    // preprocessing: fp16 conversion + weight transpose to [e][n][k]
    cvt_x_kernel<<<(TOKENS * HIDDEN) / (256 * 4), 256>>>(x);
    transpose_cvt_kernel<<<dim3(INTER / 32, HIDDEN / 32, NEXP), 256>>>(wg, 0, HIDDEN, INTER);
    transpose_cvt_kernel<<<dim3(INTER / 32, HIDDEN / 32, NEXP), 256>>>(wu, 1, HIDDEN, INTER);
    transpose_cvt_kernel<<<dim3(HIDDEN / 32, INTER / 32, NEXP), 256>>>(wd, 2, INTER, HIDDEN);

    dim3 g1(INTER / 64, TOKENS / 64, NEXP);     // 22 x 32 x 8
    gateup_kernel<<<g1, 256, SMEM_BYTES>>>();

    dim3 g2(HIDDEN / 128, TOKENS / 64, NEXP);   // 16 x 32 x 8
    down_kernel<<<g2, 256, SMEM_BYTES>>>();

    size_t total4 = (size_t)TOKENS * HIDDEN / 4;
    combine_kernel<<<(unsigned)((total4 + 255) / 256), 256>>>(out);
}

// round 10
// speedup vs baseline: 3.7042x; 1.0269x over previous
#include <cuda_runtime.h>
#include <cuda_fp16.h>
#include <cstdint>
#include <math.h>

#define TOKENS 2048
#define HIDDEN 2048
#define INTER  1408
#define NEXP   8
#define KTH    64          // k elements per tile (halfs) = 128B rows
#define STAGES 3

#define AT_B    (64  * 144)        // A tile bytes  (9216)   row stride 144B
#define BT_B    (128 * 144)        // B tile bytes  (18432)
#define STAGE_B (AT_B + BT_B)      // 27648
#define SMEM_BYTES (256 + STAGES * STAGE_B)   // 83200

// ---------------- device scratch (no allocation) ----------------
__device__ int    g_counts[NEXP];
__device__ int    g_pairs[NEXP * TOKENS];                 // encoded (t<<1)|slot
__device__ float  g_wts[TOKENS * 2];                      // combine weight per (t,slot)
__device__ __half g_x_h[(size_t)TOKENS * HIDDEN];         // x in fp16
__device__ __half g_wg_h[(size_t)NEXP * HIDDEN * INTER];  // w_gate fp16, [e][n][k]
__device__ __half g_wu_h[(size_t)NEXP * HIDDEN * INTER];  // w_up   fp16, [e][n][k]
__device__ __half g_wd_h[(size_t)NEXP * INTER * HIDDEN];  // w_down fp16, [e][n][k]
__device__ __half g_hbuf_h[(size_t)TOKENS * 2 * INTER];   // gated intermediate fp16

// m16n8k16 fp16 MMA, fp32 accumulate (standard PTX, sm_80+)
__device__ __forceinline__ void mma_f16(float* c, const uint32_t* a,
                                        uint32_t b0, uint32_t b1) {
    asm volatile(
        "mma.sync.aligned.m16n8k16.row.col.f32.f16.f16.f32 "
        "{%0,%1,%2,%3}, {%4,%5,%6,%7}, {%8,%9}, {%0,%1,%2,%3};"
        : "+f"(c[0]), "+f"(c[1]), "+f"(c[2]), "+f"(c[3])
        : "r"(a[0]), "r"(a[1]), "r"(a[2]), "r"(a[3]), "r"(b0), "r"(b1));
}

// ldmatrix x4 (b16): 4 8x8 fp16 matrices
__device__ __forceinline__ void ldsm4(uint32_t* r, uint32_t addr) {
    asm volatile("ldmatrix.sync.aligned.m8n8.x4.shared.b16 {%0,%1,%2,%3}, [%4];"
        : "=r"(r[0]), "=r"(r[1]), "=r"(r[2]), "=r"(r[3]) : "r"(addr));
}

__device__ __forceinline__ void cp16(uint32_t dst, const void* src, int sz) {
    asm volatile("cp.async.cg.shared.global [%0], [%1], 16, %2;"
                 :: "r"(dst), "l"(src), "r"(sz) : "memory");
}
#define CP_COMMIT() asm volatile("cp.async.commit_group;" ::: "memory")
#define CP_WAIT1()  asm volatile("cp.async.wait_group 1;" ::: "memory")

__device__ __forceinline__ uint32_t hpack(float a, float b) {
    __half2 h = __floats2half2_rn(a, b);
    return *(uint32_t*)&h;
}

// ---------------- kernel 0: zero counters ----------------
__global__ void zero_counts_kernel() {
    if (threadIdx.x < NEXP) g_counts[threadIdx.x] = 0;
}

// ---------------- zero output (atomicAdd target) ----------------
__global__ __launch_bounds__(256) void zero_out_kernel(float* __restrict__ out)
{
    size_t i = ((size_t)blockIdx.x * blockDim.x + threadIdx.x) * 4;
    *(float4*)(out + i) = make_float4(0.f, 0.f, 0.f, 0.f);
}

// ---------------- preprocessing: transpose+convert weights to fp16 ----------------
// src [e][K][N] (n contiguous, fp32) -> dst [e][N][K] (k contiguous, fp16)
__global__ __launch_bounds__(256) void transpose_cvt_kernel(
    const float* __restrict__ src, int which, int K, int N)
{
    __half* dst = (which == 0) ? g_wg_h : (which == 1) ? g_wu_h : g_wd_h;
    __shared__ uint32_t tile[32][33];   // one fp16 value per slot (low 16 bits)
    const size_t eoff = (size_t)blockIdx.z * K * N;
    const int n0 = blockIdx.x * 32;
    const int k0 = blockIdx.y * 32;
    const int t  = threadIdx.x;
    {
        int kr  = t >> 3;
        int nc4 = (t & 7) * 4;
        float4 v = *(const float4*)(src + eoff + (size_t)(k0 + kr) * N + n0 + nc4);
        tile[kr][nc4 + 0] = (uint32_t)__half_as_ushort(__float2half_rn(v.x));
        tile[kr][nc4 + 1] = (uint32_t)__half_as_ushort(__float2half_rn(v.y));
        tile[kr][nc4 + 2] = (uint32_t)__half_as_ushort(__float2half_rn(v.z));
        tile[kr][nc4 + 3] = (uint32_t)__half_as_ushort(__float2half_rn(v.w));
    }
    __syncthreads();
    {
        int nr  = t >> 3;
        int kc4 = (t & 7) * 4;
        uint2 o;
        o.x = tile[kc4 + 0][nr] | (tile[kc4 + 1][nr] << 16);
        o.y = tile[kc4 + 2][nr] | (tile[kc4 + 3][nr] << 16);
        *(uint2*)(dst + eoff + (size_t)(n0 + nr) * K + k0 + kc4) = o;
    }
}

// x -> fp16 (layout unchanged)
__global__ __launch_bounds__(256) void cvt_x_kernel(const float* __restrict__ src)
{
    size_t i = ((size_t)blockIdx.x * blockDim.x + threadIdx.x) * 4;
    float4 v = *(const float4*)(src + i);
    uint2 o;
    o.x = hpack(v.x, v.y);
    o.y = hpack(v.z, v.w);
    *(uint2*)(g_x_h + i) = o;
}

// ---------------- kernel 1: router ----------------
__global__ __launch_bounds__(256) void router_kernel(
    const float* __restrict__ x, const float* __restrict__ wr)
{
    int t = blockIdx.x;
    __shared__ float red[256][NEXP];
    float acc[NEXP];
#pragma unroll
    for (int e = 0; e < NEXP; e++) acc[e] = 0.f;
    const float* xr = x + (size_t)t * HIDDEN;
    for (int h = threadIdx.x; h < HIDDEN; h += 256) {
        float xv = xr[h];
        const float* w = wr + (size_t)h * NEXP;
#pragma unroll
        for (int e = 0; e < NEXP; e++) acc[e] += xv * w[e];
    }
#pragma unroll
    for (int e = 0; e < NEXP; e++) red[threadIdx.x][e] = acc[e];
    __syncthreads();
    for (int s = 128; s > 0; s >>= 1) {
        if (threadIdx.x < s) {
#pragma unroll
            for (int e = 0; e < NEXP; e++)
                red[threadIdx.x][e] += red[threadIdx.x + s][e];
        }
        __syncthreads();
    }
    if (threadIdx.x == 0) {
        float l[NEXP];
#pragma unroll
        for (int e = 0; e < NEXP; e++) l[e] = red[0][e];
        int i0 = 0;
#pragma unroll
        for (int e = 1; e < NEXP; e++) if (l[e] > l[i0]) i0 = e;
        int i1 = -1;
#pragma unroll
        for (int e = 0; e < NEXP; e++) {
            if (e == i0) continue;
            if (i1 < 0 || l[e] > l[i1]) i1 = e;
        }
        float w0 = 1.f / (1.f + __expf(l[i1] - l[i0]));
        float w1 = 1.f - w0;
        int p0 = atomicAdd(&g_counts[i0], 1);
        g_pairs[i0 * TOKENS + p0] = (t << 1);
        int p1 = atomicAdd(&g_counts[i1], 1);
        g_pairs[i1 * TOKENS + p1] = (t << 1) | 1;
        g_wts[(t << 1)]     = w0;
        g_wts[(t << 1) | 1] = w1;
    }
}

// ---------------- kernel 2: grouped gate+up GEMM (fp16, 64m x 64n) ----------------
// grid: x = m-tile (fastest) so concurrent CTAs share the B tile via L2
__global__ __launch_bounds__(256, 2) void gateup_kernel()
{
    const int e   = blockIdx.z;
    const int cnt = g_counts[e];
    const int m0  = blockIdx.x * 64;
    if (m0 >= cnt) return;
    const int n0  = blockIdx.y * 64;

    extern __shared__ __align__(16) uint32_t dsm[];
    int* rows_sh = (int*)dsm;
    const uint32_t sb = (uint32_t)__cvta_generic_to_shared(dsm);

    const int tid  = threadIdx.x;
    const int wid  = tid >> 5;
    const int lane = tid & 31;
    const int gr   = lane >> 2;
    const int tg   = lane & 3;
    const int wm   = (wid & 1) * 32;   // warp m offset
    const int wn   = (wid >> 1) * 32;  // warp B-row offset

    if (tid < 64) {
        int m = m0 + tid;
        rows_sh[tid] = (m < cnt) ? g_pairs[e * TOKENS + m] : -1;
    }
    __syncthreads();

    const size_t eoff = (size_t)e * HIDDEN * INTER;

    // staging: A 2 chunks of 16B, B 4 chunks of 16B per thread (8 chunks/row)
    const __half* asrc[2];
    int  asz[2];
    uint32_t adst[2];   // byte offset within stage
#pragma unroll
    for (int i = 0; i < 2; i++) {
        int q  = tid + 256 * i;
        int m  = q >> 3;
        int c  = q & 7;
        int pr = rows_sh[m];
        asz[i]  = (pr >= 0) ? 16 : 0;
        asrc[i] = g_x_h + (size_t)((pr >= 0) ? (pr >> 1) : 0) * HIDDEN + c * 8;
        adst[i] = (uint32_t)(m * 144 + c * 16);
    }
    const __half* bsrc[4];
    uint32_t bdst[4];
#pragma unroll
    for (int i = 0; i < 4; i++) {
        int q    = tid + 256 * i;
        int r    = q >> 3;               // B tile row 0..127
        int c    = q & 7;
        int half = (r >> 4) & 1;         // 0 gate / 1 up (16-row granularity)
        int nn   = n0 + (r >> 5) * 16 + (r & 15);
        bsrc[i]  = (half ? g_wu_h : g_wg_h) + eoff + (size_t)nn * HIDDEN + c * 8;
        bdst[i]  = (uint32_t)(r * 144 + c * 16);
    }

    const int rlo  = lane & 15;
    const int kadd = (lane >> 4) * 8;

    float acc[2][4][4];
#pragma unroll
    for (int i = 0; i < 2; i++)
#pragma unroll
        for (int j = 0; j < 4; j++)
#pragma unroll
            for (int c = 0; c < 4; c++) acc[i][j][c] = 0.f;

    // prologue
#pragma unroll
    for (int s = 0; s < STAGES - 1; s++) {
        uint32_t ab = sb + 256 + s * STAGE_B;
        uint32_t bb = ab + AT_B;
        size_t ko = (size_t)s * KTH;
#pragma unroll
        for (int i = 0; i < 2; i++) cp16(ab + adst[i], asrc[i] + ko, asz[i]);
#pragma unroll
        for (int i = 0; i < 4; i++) cp16(bb + bdst[i], bsrc[i] + ko, 16);
        CP_COMMIT();
    }

    const int NT = HIDDEN / KTH;   // 32
    int rd = 0, wr = STAGES - 1;
    for (int kt = 0; kt < NT; kt++) {
        CP_WAIT1();
        __syncthreads();

        if (kt + STAGES - 1 < NT) {
            uint32_t ab = sb + 256 + wr * STAGE_B;
            uint32_t bb = ab + AT_B;
            size_t ko = (size_t)(kt + STAGES - 1) * KTH;
#pragma unroll
            for (int i = 0; i < 2; i++) cp16(ab + adst[i], asrc[i] + ko, asz[i]);
#pragma unroll
            for (int i = 0; i < 4; i++) cp16(bb + bdst[i], bsrc[i] + ko, 16);
        }
        CP_COMMIT();

        const uint32_t Ab = sb + 256 + rd * STAGE_B;
        const uint32_t Bb = Ab + AT_B;
#pragma unroll
        for (int ks = 0; ks < 4; ks++) {
            const int k = ks * 16;
            uint32_t a[2][4];
#pragma unroll
            for (int mi = 0; mi < 2; mi++)
                ldsm4(a[mi], Ab + (uint32_t)((wm + mi * 16 + rlo) * 144 + (k + kadd) * 2));
            uint32_t b0[4], b1[4];
            ldsm4(b0, Bb + (uint32_t)((wn + rlo)      * 144 + (k + kadd) * 2));
            ldsm4(b1, Bb + (uint32_t)((wn + 16 + rlo) * 144 + (k + kadd) * 2));
#pragma unroll
            for (int mi = 0; mi < 2; mi++) {
                mma_f16(acc[mi][0], a[mi], b0[0], b0[2]);
                mma_f16(acc[mi][1], a[mi], b0[1], b0[3]);
                mma_f16(acc[mi][2], a[mi], b1[0], b1[2]);
                mma_f16(acc[mi][3], a[mi], b1[1], b1[3]);
            }
        }
        rd = (rd == STAGES - 1) ? 0 : rd + 1;
        wr = (wr == STAGES - 1) ? 0 : wr + 1;
    }

    // epilogue: nj 0,1 = gate, nj 2,3 = up at same output cols; hbuf fp16
    const int colbase = n0 + (wid >> 1) * 16 + 2 * tg;
#pragma unroll
    for (int mi = 0; mi < 2; mi++) {
#pragma unroll
        for (int half = 0; half < 2; half++) {
            int row = wm + mi * 16 + gr + half * 8;
            int pr  = rows_sh[row];
            if (pr < 0) continue;
            float wt = g_wts[pr];
            __half* hrow = g_hbuf_h + (size_t)pr * INTER;
#pragma unroll
            for (int nj = 0; nj < 2; nj++) {
                float g0 = acc[mi][nj][half * 2 + 0];
                float g1 = acc[mi][nj][half * 2 + 1];
                float u0 = acc[mi][nj + 2][half * 2 + 0];
                float u1 = acc[mi][nj + 2][half * 2 + 1];
                float h0 = (g0 / (1.f + __expf(-g0))) * u0 * wt;
                float h1 = (g1 / (1.f + __expf(-g1))) * u1 * wt;
                *(uint32_t*)&hrow[colbase + nj * 8] = hpack(h0, h1);
            }
        }
    }
}

// ---------------- kernel 3: grouped down GEMM (fp16, 64m x 128n) ----------------
// grid: x = m-tile (fastest). Epilogue atomicAdds directly into out[t][h]:
// exactly two contributions per element (slot 0/1); IEEE add is commutative,
// so the result is bitwise deterministic regardless of arrival order.
__global__ __launch_bounds__(256, 2) void down_kernel(float* __restrict__ out)
{
    const int e   = blockIdx.z;
    const int cnt = g_counts[e];
    const int m0  = blockIdx.x * 64;
    if (m0 >= cnt) return;
    const int n0  = blockIdx.y * 128;

    extern __shared__ __align__(16) uint32_t dsm[];
    int* rows_sh = (int*)dsm;
    const uint32_t sb = (uint32_t)__cvta_generic_to_shared(dsm);

    const int tid  = threadIdx.x;
    const int wid  = tid >> 5;
    const int lane = tid & 31;
    const int gr   = lane >> 2;
    const int tg   = lane & 3;
    const int wm   = (wid & 1) * 32;
    const int wn   = (wid >> 1) * 32;

    if (tid < 64) {
        int m = m0 + tid;
        rows_sh[tid] = (m < cnt) ? g_pairs[e * TOKENS + m] : -1;
    }
    __syncthreads();

    const size_t eoff = (size_t)e * HIDDEN * INTER;

    const __half* asrc[2];
    int  asz[2];
    uint32_t adst[2];
#pragma unroll
    for (int i = 0; i < 2; i++) {
        int q  = tid + 256 * i;
        int m  = q >> 3;
        int c  = q & 7;
        int pr = rows_sh[m];
        asz[i]  = (pr >= 0) ? 16 : 0;
        asrc[i] = g_hbuf_h + (size_t)((pr >= 0) ? pr : 0) * INTER + c * 8;
        adst[i] = (uint32_t)(m * 144 + c * 16);
    }
    const __half* bsrc[4];
    uint32_t bdst[4];
#pragma unroll
    for (int i = 0; i < 4; i++) {
        int q   = tid + 256 * i;
        int r   = q >> 3;
        int c   = q & 7;
        bsrc[i] = g_wd_h + eoff + (size_t)(n0 + r) * INTER + c * 8;
        bdst[i] = (uint32_t)(r * 144 + c * 16);
    }

    const int rlo  = lane & 15;
    const int kadd = (lane >> 4) * 8;

    float acc[2][4][4];
#pragma unroll
    for (int i = 0; i < 2; i++)
#pragma unroll
        for (int j = 0; j < 4; j++)
#pragma unroll
            for (int c = 0; c < 4; c++) acc[i][j][c] = 0.f;

#pragma unroll
    for (int s = 0; s < STAGES - 1; s++) {
        uint32_t ab = sb + 256 + s * STAGE_B;
        uint32_t bb = ab + AT_B;
        size_t ko = (size_t)s * KTH;
#pragma unroll
        for (int i = 0; i < 2; i++) cp16(ab + adst[i], asrc[i] + ko, asz[i]);
#pragma unroll
        for (int i = 0; i < 4; i++) cp16(bb + bdst[i], bsrc[i] + ko, 16);
        CP_COMMIT();
    }

    const int NT = INTER / KTH;   // 22
    int rd = 0, wr = STAGES - 1;
    for (int kt = 0; kt < NT; kt++) {
        CP_WAIT1();
        __syncthreads();

        if (kt + STAGES - 1 < NT) {
            uint32_t ab = sb + 256 + wr * STAGE_B;
            uint32_t bb = ab + AT_B;
            size_t ko = (size_t)(kt + STAGES - 1) * KTH;
#pragma unroll
            for (int i = 0; i < 2; i++) cp16(ab + adst[i], asrc[i] + ko, asz[i]);
#pragma unroll
            for (int i = 0; i < 4; i++) cp16(bb + bdst[i], bsrc[i] + ko, 16);
        }
        CP_COMMIT();

        const uint32_t Ab = sb + 256 + rd * STAGE_B;
        const uint32_t Bb = Ab + AT_B;
#pragma unroll
        for (int ks = 0; ks < 4; ks++) {
            const int k = ks * 16;
            uint32_t a[2][4];
#pragma unroll
            for (int mi = 0; mi < 2; mi++)
                ldsm4(a[mi], Ab + (uint32_t)((wm + mi * 16 + rlo) * 144 + (k + kadd) * 2));
            uint32_t b0[4], b1[4];
            ldsm4(b0, Bb + (uint32_t)((wn + rlo)      * 144 + (k + kadd) * 2));
            ldsm4(b1, Bb + (uint32_t)((wn + 16 + rlo) * 144 + (k + kadd) * 2));
#pragma unroll
            for (int mi = 0; mi < 2; mi++) {
                mma_f16(acc[mi][0], a[mi], b0[0], b0[2]);
                mma_f16(acc[mi][1], a[mi], b0[1], b0[3]);
                mma_f16(acc[mi][2], a[mi], b1[0], b1[2]);
                mma_f16(acc[mi][3], a[mi], b1[1], b1[3]);
            }
        }
        rd = (rd == STAGES - 1) ? 0 : rd + 1;
        wr = (wr == STAGES - 1) ? 0 : wr + 1;
    }

    // fused combine: atomicAdd both slots directly into out
    const int colbase = n0 + wn + 2 * tg;
#pragma unroll
    for (int mi = 0; mi < 2; mi++) {
#pragma unroll
        for (int half = 0; half < 2; half++) {
            int row = wm + mi * 16 + gr + half * 8;
            int pr  = rows_sh[row];
            if (pr < 0) continue;
            float* orow = out + (size_t)(pr >> 1) * HIDDEN;
#pragma unroll
            for (int nj = 0; nj < 4; nj++) {
                atomicAdd(&orow[colbase + nj * 8 + 0], acc[mi][nj][half * 2 + 0]);
                atomicAdd(&orow[colbase + nj * 8 + 1], acc[mi][nj][half * 2 + 1]);
            }
        }
    }
}

// ---------------- launch ----------------
extern "C" void kernel_launch(void* const* d_in, const int* in_sizes, int n_in,
                              void* d_out, int out_size)
{
    const float* x  = (const float*)d_in[0];
    const float* wr = (const float*)d_in[1];
    const float* wg = (const float*)d_in[2];
    const float* wu = (const float*)d_in[3];
    const float* wd = (const float*)d_in[4];
    float* out = (float*)d_out;

    cudaFuncSetAttribute(gateup_kernel, cudaFuncAttributeMaxDynamicSharedMemorySize, SMEM_BYTES);
    cudaFuncSetAttribute(down_kernel,  cudaFuncAttributeMaxDynamicSharedMemorySize, SMEM_BYTES);

    zero_counts_kernel<<<1, 32>>>();
    zero_out_kernel<<<(TOKENS * HIDDEN) / (256 * 4), 256>>>(out);
    router_kernel<<<TOKENS, 256>>>(x, wr);

    // preprocessing: fp16 conversion + weight transpose to [e][n][k]
    cvt_x_kernel<<<(TOKENS * HIDDEN) / (256 * 4), 256>>>(x);
    transpose_cvt_kernel<<<dim3(INTER / 32, HIDDEN / 32, NEXP), 256>>>(wg, 0, HIDDEN, INTER);
    transpose_cvt_kernel<<<dim3(INTER / 32, HIDDEN / 32, NEXP), 256>>>(wu, 1, HIDDEN, INTER);
    transpose_cvt_kernel<<<dim3(HIDDEN / 32, INTER / 32, NEXP), 256>>>(wd, 2, INTER, HIDDEN);

    dim3 g1(TOKENS / 64, INTER / 64, NEXP);     // m fastest: L2 B-tile sharing
    gateup_kernel<<<g1, 256, SMEM_BYTES>>>();

    dim3 g2(TOKENS / 64, HIDDEN / 128, NEXP);   // m fastest
    down_kernel<<<g2, 256, SMEM_BYTES>>>(out);
}